// round 1
// baseline (speedup 1.0000x reference)
#include <cuda_runtime.h>
#include <cuda_bf16.h>
#include <math.h>

#define B_  2
#define S_  2048
#define D_  1024
#define H_  16
#define HD_ 64
#define N_  (B_*S_)   // 4096

// Scratch (allocation-free rule: __device__ globals)
__device__ float g_q[N_*D_];
__device__ float g_k[N_*D_];
__device__ float g_v[N_*D_];
__device__ float g_o[N_*D_];

// ---------------------------------------------------------------------------
// GEMM: C = A[N,K] @ W[M,K]^T + bias, K = 1024, 64x64 tile, 4x4 micro-tile
// MODE 0: C written as [N, M] (row-major)
// MODE 1: C written as [B, H, S, HD] (split-head layout), tile col-block == one head
// ---------------------------------------------------------------------------
template<int MODE>
__global__ __launch_bounds__(256)
void gemm_bias_kernel(const float* __restrict__ A,
                      const float* __restrict__ W,
                      const float* __restrict__ bias,
                      float* __restrict__ C)
{
    const int K = D_;
    __shared__ float As[16][64];   // [kk][row]
    __shared__ float Bs[16][64];   // [kk][col]

    const int tx = threadIdx.x, ty = threadIdx.y;
    const int tid = ty * 16 + tx;
    const int row0 = blockIdx.y * 64;
    const int col0 = blockIdx.x * 64;

    float acc[4][4];
#pragma unroll
    for (int i = 0; i < 4; i++)
#pragma unroll
        for (int j = 0; j < 4; j++) acc[i][j] = 0.f;

    const int lr = tid >> 2;        // 0..63 (row within tile)
    const int lk = tid & 3;         // 0..3  (float4 slot within 16 k)

    for (int k0 = 0; k0 < K; k0 += 16) {
        float4 a4 = *(const float4*)(A + (size_t)(row0 + lr) * K + k0 + lk * 4);
        float4 b4 = *(const float4*)(W + (size_t)(col0 + lr) * K + k0 + lk * 4);
        As[lk*4+0][lr] = a4.x; As[lk*4+1][lr] = a4.y;
        As[lk*4+2][lr] = a4.z; As[lk*4+3][lr] = a4.w;
        Bs[lk*4+0][lr] = b4.x; Bs[lk*4+1][lr] = b4.y;
        Bs[lk*4+2][lr] = b4.z; Bs[lk*4+3][lr] = b4.w;
        __syncthreads();

#pragma unroll
        for (int kk = 0; kk < 16; kk++) {
            float4 av = *(const float4*)&As[kk][ty * 4];
            float4 bv = *(const float4*)&Bs[kk][tx * 4];
            float a[4] = {av.x, av.y, av.z, av.w};
            float b[4] = {bv.x, bv.y, bv.z, bv.w};
#pragma unroll
            for (int i = 0; i < 4; i++)
#pragma unroll
                for (int j = 0; j < 4; j++)
                    acc[i][j] = fmaf(a[i], b[j], acc[i][j]);
        }
        __syncthreads();
    }

    float4 bb = *(const float4*)(bias + col0 + tx * 4);
    float bj[4] = {bb.x, bb.y, bb.z, bb.w};

#pragma unroll
    for (int i = 0; i < 4; i++) {
        int n = row0 + ty * 4 + i;
        float4 o4;
        o4.x = acc[i][0] + bj[0];
        o4.y = acc[i][1] + bj[1];
        o4.z = acc[i][2] + bj[2];
        o4.w = acc[i][3] + bj[3];
        if (MODE == 0) {
            *(float4*)(C + (size_t)n * D_ + col0 + tx * 4) = o4;
        } else {
            // split heads: d = col0 + tx*4 + j ; col0 is a multiple of 64 == HD
            int b  = n >> 11;        // n / 2048
            int s  = n & 2047;
            int h  = col0 >> 6;
            int hd = tx * 4;
            *(float4*)(C + (((size_t)(b * H_ + h) * S_) + s) * HD_ + hd) = o4;
        }
    }
}

// ---------------------------------------------------------------------------
// Fused attention: per CTA = one (b,h) head and a 64-row Q tile.
// Online softmax (flash style). Dyn smem: Qs_t[64][68], Ks_t[64][68],
// Vs[64][64], Ps[64][65].
// ---------------------------------------------------------------------------
__device__ __forceinline__ float rmax16(float v) {
#pragma unroll
    for (int o = 8; o; o >>= 1) v = fmaxf(v, __shfl_xor_sync(0xffffffffu, v, o));
    return v;
}
__device__ __forceinline__ float rsum16(float v) {
#pragma unroll
    for (int o = 8; o; o >>= 1) v += __shfl_xor_sync(0xffffffffu, v, o);
    return v;
}

#define QS_STRIDE 68
#define KS_STRIDE 68
#define PS_STRIDE 65

__global__ __launch_bounds__(256)
void attn_kernel(const float* __restrict__ Q,
                 const float* __restrict__ Kg,
                 const float* __restrict__ Vg,
                 float* __restrict__ O)
{
    extern __shared__ float sm[];
    float* Qs = sm;                         // [hd][qrow]  64*68
    float* Ks = Qs + 64 * QS_STRIDE;        // [hd][kpos]  64*68
    float* Vs = Ks + 64 * KS_STRIDE;        // [kpos][hd]  64*64
    float* Ps = Vs + 64 * 64;               // [qrow][kpos] 64*65

    const int tx = threadIdx.x, ty = threadIdx.y;
    const int tid = ty * 16 + tx;
    const int q0 = blockIdx.x * 64;
    const int bh = blockIdx.y;              // b*H + h
    const int b  = bh / H_;
    const int h  = bh % H_;

    const float scale = 0.125f;             // 1/sqrt(64)
    const float* qbase = Q + (size_t)bh * S_ * HD_ + (size_t)q0 * HD_;
    const float* kbase = Kg + (size_t)bh * S_ * HD_;
    const float* vbase = Vg + (size_t)bh * S_ * HD_;

    // Load Q tile transposed (pre-scaled)
#pragma unroll
    for (int i = 0; i < 4; i++) {
        int idx4 = tid + i * 256;
        int r  = idx4 >> 4;
        int c4 = idx4 & 15;
        float4 q4 = *(const float4*)(qbase + r * 64 + c4 * 4);
        Qs[(c4*4+0) * QS_STRIDE + r] = q4.x * scale;
        Qs[(c4*4+1) * QS_STRIDE + r] = q4.y * scale;
        Qs[(c4*4+2) * QS_STRIDE + r] = q4.z * scale;
        Qs[(c4*4+3) * QS_STRIDE + r] = q4.w * scale;
    }

    float m_i[4], l_i[4], o_acc[4][4];
#pragma unroll
    for (int i = 0; i < 4; i++) {
        m_i[i] = -1e30f; l_i[i] = 0.f;
#pragma unroll
        for (int j = 0; j < 4; j++) o_acc[i][j] = 0.f;
    }

    for (int kt = 0; kt < S_ / 64; kt++) {
        __syncthreads();   // previous PV reads of Ks/Vs done
        // Load K tile transposed, V tile natural
#pragma unroll
        for (int i = 0; i < 4; i++) {
            int idx4 = tid + i * 256;
            int r  = idx4 >> 4;
            int c4 = idx4 & 15;
            float4 k4 = *(const float4*)(kbase + (size_t)(kt * 64 + r) * 64 + c4 * 4);
            Ks[(c4*4+0) * KS_STRIDE + r] = k4.x;
            Ks[(c4*4+1) * KS_STRIDE + r] = k4.y;
            Ks[(c4*4+2) * KS_STRIDE + r] = k4.z;
            Ks[(c4*4+3) * KS_STRIDE + r] = k4.w;
            float4 v4 = *(const float4*)(vbase + (size_t)(kt * 64 + r) * 64 + c4 * 4);
            *(float4*)&Vs[r * 64 + c4 * 4] = v4;
        }
        __syncthreads();

        // S = Q K^T (scaled)
        float s_f[4][4];
#pragma unroll
        for (int i = 0; i < 4; i++)
#pragma unroll
            for (int j = 0; j < 4; j++) s_f[i][j] = 0.f;

#pragma unroll
        for (int kk = 0; kk < 64; kk++) {
            float4 av = *(const float4*)&Qs[kk * QS_STRIDE + ty * 4];
            float4 bv = *(const float4*)&Ks[kk * KS_STRIDE + tx * 4];
            float a[4] = {av.x, av.y, av.z, av.w};
            float bb[4] = {bv.x, bv.y, bv.z, bv.w};
#pragma unroll
            for (int i = 0; i < 4; i++)
#pragma unroll
                for (int j = 0; j < 4; j++)
                    s_f[i][j] = fmaf(a[i], bb[j], s_f[i][j]);
        }

        // online softmax update (rows = ty*4+i, shared among the 16 tx lanes)
#pragma unroll
        for (int i = 0; i < 4; i++) {
            float mt = fmaxf(fmaxf(s_f[i][0], s_f[i][1]), fmaxf(s_f[i][2], s_f[i][3]));
            mt = rmax16(mt);
            float m_new = fmaxf(m_i[i], mt);
            float alpha = __expf(m_i[i] - m_new);
            float rs = 0.f;
#pragma unroll
            for (int j = 0; j < 4; j++) {
                float p = __expf(s_f[i][j] - m_new);
                s_f[i][j] = p;
                rs += p;
            }
            rs = rsum16(rs);
            l_i[i] = l_i[i] * alpha + rs;
            m_i[i] = m_new;
#pragma unroll
            for (int j = 0; j < 4; j++) o_acc[i][j] *= alpha;
            // stash P
#pragma unroll
            for (int j = 0; j < 4; j++)
                Ps[(ty * 4 + i) * PS_STRIDE + tx * 4 + j] = s_f[i][j];
        }
        __syncthreads();

        // O += P @ V
#pragma unroll
        for (int kk = 0; kk < 64; kk++) {
            float4 vv = *(const float4*)&Vs[kk * 64 + tx * 4];
            float v0 = vv.x, v1 = vv.y, v2 = vv.z, v3 = vv.w;
#pragma unroll
            for (int i = 0; i < 4; i++) {
                float p = Ps[(ty * 4 + i) * PS_STRIDE + kk];
                o_acc[i][0] = fmaf(p, v0, o_acc[i][0]);
                o_acc[i][1] = fmaf(p, v1, o_acc[i][1]);
                o_acc[i][2] = fmaf(p, v2, o_acc[i][2]);
                o_acc[i][3] = fmaf(p, v3, o_acc[i][3]);
            }
        }
    }

    // finalize: O written as [N, D] (merge heads)
#pragma unroll
    for (int i = 0; i < 4; i++) {
        float inv = 1.f / l_i[i];
        int n = b * S_ + q0 + ty * 4 + i;
        float4 o4;
        o4.x = o_acc[i][0] * inv;
        o4.y = o_acc[i][1] * inv;
        o4.z = o_acc[i][2] * inv;
        o4.w = o_acc[i][3] * inv;
        *(float4*)(O + (size_t)n * D_ + h * 64 + tx * 4) = o4;
    }
}

// ---------------------------------------------------------------------------
extern "C" void kernel_launch(void* const* d_in, const int* in_sizes, int n_in,
                              void* d_out, int out_size)
{
    const float* x  = (const float*)d_in[0];
    const float* Wq = (const float*)d_in[1];
    const float* bq = (const float*)d_in[2];
    const float* Wk = (const float*)d_in[3];
    const float* bk = (const float*)d_in[4];
    const float* Wv = (const float*)d_in[5];
    const float* bv = (const float*)d_in[6];
    const float* Wo = (const float*)d_in[7];
    const float* bo = (const float*)d_in[8];
    float* out = (float*)d_out;

    float *qp, *kp, *vp, *op;
    cudaGetSymbolAddress((void**)&qp, g_q);
    cudaGetSymbolAddress((void**)&kp, g_k);
    cudaGetSymbolAddress((void**)&vp, g_v);
    cudaGetSymbolAddress((void**)&op, g_o);

    dim3 thr(16, 16);
    dim3 gemm_grid(D_ / 64, N_ / 64);

    gemm_bias_kernel<1><<<gemm_grid, thr>>>(x, Wq, bq, qp);
    gemm_bias_kernel<1><<<gemm_grid, thr>>>(x, Wk, bk, kp);
    gemm_bias_kernel<1><<<gemm_grid, thr>>>(x, Wv, bv, vp);

    const int smem_bytes = (64*QS_STRIDE + 64*KS_STRIDE + 64*64 + 64*PS_STRIDE) * 4;
    cudaFuncSetAttribute(attn_kernel, cudaFuncAttributeMaxDynamicSharedMemorySize, smem_bytes);
    attn_kernel<<<dim3(S_ / 64, B_ * H_), thr, smem_bytes>>>(qp, kp, vp, op);

    gemm_bias_kernel<0><<<gemm_grid, thr>>>(op, Wo, bo, out);
}

// round 3
// speedup vs baseline: 1.6507x; 1.6507x over previous
#include <cuda_runtime.h>
#include <cuda_bf16.h>
#include <stdint.h>
#include <math.h>

#define B_  2
#define S_  2048
#define D_  1024
#define H_  16
#define HD_ 64
#define N_  (B_*S_)   // 4096

// Scratch (allocation-free rule: __device__ globals)
__device__ float g_q[N_*D_];
__device__ float g_k[N_*D_];
__device__ float g_v[N_*D_];
__device__ float g_o[N_*D_];

// ---------------------------------------------------------------------------
// Base-PTX helpers (NO tcgen05 / arch-suffix features: harness compiles
// with a non-'a' PTX target, so only sm_80-era base instructions are legal)
// ---------------------------------------------------------------------------
__device__ __forceinline__ void cp16(uint32_t dst, const void* src) {
    asm volatile("cp.async.cg.shared.global [%0], [%1], 16;"
                 :: "r"(dst), "l"(__cvta_generic_to_global(src)));
}
__device__ __forceinline__ void cp_commit() {
    asm volatile("cp.async.commit_group;");
}
template<int N> __device__ __forceinline__ void cp_wait() {
    asm volatile("cp.async.wait_group %0;" :: "n"(N));
}
__device__ __forceinline__ uint32_t f2tf32(float f) {
    uint32_t r;
    asm("cvt.rna.tf32.f32 %0, %1;" : "=r"(r) : "f"(f));
    return r;
}
__device__ __forceinline__ void mma_tf32(float c[4],
                                         const uint32_t a[4],
                                         const uint32_t b[2]) {
    asm volatile(
        "mma.sync.aligned.m16n8k8.row.col.f32.tf32.tf32.f32 "
        "{%0,%1,%2,%3}, {%4,%5,%6,%7}, {%8,%9}, {%0,%1,%2,%3};"
        : "+f"(c[0]), "+f"(c[1]), "+f"(c[2]), "+f"(c[3])
        : "r"(a[0]), "r"(a[1]), "r"(a[2]), "r"(a[3]),
          "r"(b[0]), "r"(b[1]));
}

// ---------------------------------------------------------------------------
// tf32 tensor-core GEMM: C[N_,1024] = A[N_,1024] @ W[1024,1024]^T + bias
// CTA tile 128x128, 8 warps (4m x 2n), warp tile 32x64, K chunk 32, 2 stages.
// Smem row stride 36 floats -> conflict-free fragment loads.
// ---------------------------------------------------------------------------
#define TM 128
#define TN 128
#define KC 32
#define NCH (D_/KC)          // 32
#define STG 2
#define ASTR 36              // floats
#define TILE_FLOATS (TM*ASTR)        // 4608 (A == B size since TM==TN)
#define STAGE_FLOATS (2*TILE_FLOATS) // 9216
#define GEMM_SMEM (STG*STAGE_FLOATS*4) // 73728 bytes

__device__ __forceinline__ void load_chunk(const float* __restrict__ A,
                                           const float* __restrict__ W,
                                           int row0, int col0, int c,
                                           float* stage, int tid)
{
    const uint32_t abase = (uint32_t)__cvta_generic_to_shared(stage);
    const uint32_t bbase = (uint32_t)__cvta_generic_to_shared(stage + TILE_FLOATS);
    const char* asrc = (const char*)(A + (size_t)row0 * D_ + c * KC);
    const char* bsrc = (const char*)(W + (size_t)col0 * D_ + c * KC);
#pragma unroll
    for (int i = 0; i < 4; i++) {          // 128 rows x 32 floats (8 x 16B)
        int idx = tid + (i << 8);
        int r = idx >> 3, c16 = idx & 7;
        cp16(abase + (uint32_t)(r * (ASTR*4) + c16 * 16),
             asrc + (size_t)r * (D_*4) + c16 * 16);
    }
#pragma unroll
    for (int i = 0; i < 4; i++) {
        int idx = tid + (i << 8);
        int r = idx >> 3, c16 = idx & 7;
        cp16(bbase + (uint32_t)(r * (ASTR*4) + c16 * 16),
             bsrc + (size_t)r * (D_*4) + c16 * 16);
    }
    cp_commit();
}

__global__ __launch_bounds__(256, 2)
void gemm_mma_kernel(const float* __restrict__ A,
                     const float* __restrict__ W,
                     const float* __restrict__ bias,
                     float* __restrict__ C)
{
    extern __shared__ float sm[];
    const int tid  = threadIdx.x;
    const int lane = tid & 31;
    const int warp = tid >> 5;
    const int wm   = warp & 3;        // 4 m-warps
    const int wn   = warp >> 2;       // 2 n-warps
    const int row0 = blockIdx.y * TM;
    const int col0 = blockIdx.x * TN;

    const int lr = lane >> 2;         // 0..7
    const int lc = lane & 3;          // 0..3

    float c_f[2][8][4];
#pragma unroll
    for (int mi = 0; mi < 2; mi++)
#pragma unroll
        for (int ni = 0; ni < 8; ni++)
#pragma unroll
            for (int j = 0; j < 4; j++) c_f[mi][ni][j] = 0.f;

    // Prologue
    load_chunk(A, W, row0, col0, 0, sm, tid);
    load_chunk(A, W, row0, col0, 1, sm + STAGE_FLOATS, tid);

    for (int kt = 0; kt < NCH; kt++) {
        if (kt >= NCH - 1) cp_wait<0>(); else cp_wait<1>();
        __syncthreads();

        const float* As = sm + (kt & 1) * STAGE_FLOATS;
        const float* Bs = As + TILE_FLOATS;

#pragma unroll
        for (int ks = 0; ks < 4; ks++) {
            const int k0 = ks * 8 + lc;
            uint32_t a_f[2][4];
#pragma unroll
            for (int mi = 0; mi < 2; mi++) {
                int r = wm * 32 + mi * 16 + lr;
                a_f[mi][0] = f2tf32(As[r * ASTR + k0]);
                a_f[mi][1] = f2tf32(As[(r + 8) * ASTR + k0]);
                a_f[mi][2] = f2tf32(As[r * ASTR + k0 + 4]);
                a_f[mi][3] = f2tf32(As[(r + 8) * ASTR + k0 + 4]);
            }
            uint32_t b_f[8][2];
#pragma unroll
            for (int ni = 0; ni < 8; ni++) {
                int n = wn * 64 + ni * 8 + lr;
                b_f[ni][0] = f2tf32(Bs[n * ASTR + k0]);
                b_f[ni][1] = f2tf32(Bs[n * ASTR + k0 + 4]);
            }
#pragma unroll
            for (int mi = 0; mi < 2; mi++)
#pragma unroll
                for (int ni = 0; ni < 8; ni++)
                    mma_tf32(c_f[mi][ni], a_f[mi], b_f[ni]);
        }
        __syncthreads();

        if (kt + STG < NCH)
            load_chunk(A, W, row0, col0, kt + STG,
                       sm + (kt & 1) * STAGE_FLOATS, tid);
    }

    // Epilogue: bias + store
#pragma unroll
    for (int ni = 0; ni < 8; ni++) {
        int col = col0 + wn * 64 + ni * 8 + lc * 2;
        float2 bb = *(const float2*)(bias + col);
#pragma unroll
        for (int mi = 0; mi < 2; mi++) {
            int r = row0 + wm * 32 + mi * 16 + lr;
            float2 o0, o1;
            o0.x = c_f[mi][ni][0] + bb.x;
            o0.y = c_f[mi][ni][1] + bb.y;
            o1.x = c_f[mi][ni][2] + bb.x;
            o1.y = c_f[mi][ni][3] + bb.y;
            *(float2*)(C + (size_t)r * D_ + col)       = o0;
            *(float2*)(C + (size_t)(r + 8) * D_ + col) = o1;
        }
    }
}

// ---------------------------------------------------------------------------
// Fused attention (SIMT fp32; Q/K/V are [N_, D_] row-major, head h at
// cols [h*64, h*64+64)).
// ---------------------------------------------------------------------------
__device__ __forceinline__ float rmax16(float v) {
#pragma unroll
    for (int o = 8; o; o >>= 1) v = fmaxf(v, __shfl_xor_sync(0xffffffffu, v, o));
    return v;
}
__device__ __forceinline__ float rsum16(float v) {
#pragma unroll
    for (int o = 8; o; o >>= 1) v += __shfl_xor_sync(0xffffffffu, v, o);
    return v;
}

#define QS_STRIDE 68
#define KS_STRIDE 68
#define PS_STRIDE 65

__global__ __launch_bounds__(256)
void attn_kernel(const float* __restrict__ Q,
                 const float* __restrict__ Kg,
                 const float* __restrict__ Vg,
                 float* __restrict__ O)
{
    extern __shared__ float sm[];
    float* Qs = sm;
    float* Ks = Qs + 64 * QS_STRIDE;
    float* Vs = Ks + 64 * KS_STRIDE;
    float* Ps = Vs + 64 * 64;

    const int tx = threadIdx.x, ty = threadIdx.y;
    const int tid = ty * 16 + tx;
    const int q0 = blockIdx.x * 64;
    const int bh = blockIdx.y;
    const int b  = bh / H_;
    const int h  = bh % H_;

    const float scale = 0.125f;
    const float* qbase = Q  + ((size_t)(b * S_ + q0)) * D_ + h * HD_;
    const float* kbase = Kg + ((size_t)(b * S_)) * D_ + h * HD_;
    const float* vbase = Vg + ((size_t)(b * S_)) * D_ + h * HD_;

#pragma unroll
    for (int i = 0; i < 4; i++) {
        int idx4 = tid + i * 256;
        int r  = idx4 >> 4;
        int c4 = idx4 & 15;
        float4 q4 = *(const float4*)(qbase + (size_t)r * D_ + c4 * 4);
        Qs[(c4*4+0) * QS_STRIDE + r] = q4.x * scale;
        Qs[(c4*4+1) * QS_STRIDE + r] = q4.y * scale;
        Qs[(c4*4+2) * QS_STRIDE + r] = q4.z * scale;
        Qs[(c4*4+3) * QS_STRIDE + r] = q4.w * scale;
    }

    float m_i[4], l_i[4], o_acc[4][4];
#pragma unroll
    for (int i = 0; i < 4; i++) {
        m_i[i] = -1e30f; l_i[i] = 0.f;
#pragma unroll
        for (int j = 0; j < 4; j++) o_acc[i][j] = 0.f;
    }

    for (int kt = 0; kt < S_ / 64; kt++) {
        __syncthreads();
#pragma unroll
        for (int i = 0; i < 4; i++) {
            int idx4 = tid + i * 256;
            int r  = idx4 >> 4;
            int c4 = idx4 & 15;
            float4 k4 = *(const float4*)(kbase + (size_t)(kt * 64 + r) * D_ + c4 * 4);
            Ks[(c4*4+0) * KS_STRIDE + r] = k4.x;
            Ks[(c4*4+1) * KS_STRIDE + r] = k4.y;
            Ks[(c4*4+2) * KS_STRIDE + r] = k4.z;
            Ks[(c4*4+3) * KS_STRIDE + r] = k4.w;
            float4 v4 = *(const float4*)(vbase + (size_t)(kt * 64 + r) * D_ + c4 * 4);
            *(float4*)&Vs[r * 64 + c4 * 4] = v4;
        }
        __syncthreads();

        float s_f[4][4];
#pragma unroll
        for (int i = 0; i < 4; i++)
#pragma unroll
            for (int j = 0; j < 4; j++) s_f[i][j] = 0.f;

#pragma unroll
        for (int kk = 0; kk < 64; kk++) {
            float4 av = *(const float4*)&Qs[kk * QS_STRIDE + ty * 4];
            float4 bv = *(const float4*)&Ks[kk * KS_STRIDE + tx * 4];
            float a[4] = {av.x, av.y, av.z, av.w};
            float bb[4] = {bv.x, bv.y, bv.z, bv.w};
#pragma unroll
            for (int i = 0; i < 4; i++)
#pragma unroll
                for (int j = 0; j < 4; j++)
                    s_f[i][j] = fmaf(a[i], bb[j], s_f[i][j]);
        }

#pragma unroll
        for (int i = 0; i < 4; i++) {
            float mt = fmaxf(fmaxf(s_f[i][0], s_f[i][1]), fmaxf(s_f[i][2], s_f[i][3]));
            mt = rmax16(mt);
            float m_new = fmaxf(m_i[i], mt);
            float alpha = __expf(m_i[i] - m_new);
            float rs = 0.f;
#pragma unroll
            for (int j = 0; j < 4; j++) {
                float p = __expf(s_f[i][j] - m_new);
                s_f[i][j] = p;
                rs += p;
            }
            rs = rsum16(rs);
            l_i[i] = l_i[i] * alpha + rs;
            m_i[i] = m_new;
#pragma unroll
            for (int j = 0; j < 4; j++) o_acc[i][j] *= alpha;
#pragma unroll
            for (int j = 0; j < 4; j++)
                Ps[(ty * 4 + i) * PS_STRIDE + tx * 4 + j] = s_f[i][j];
        }
        __syncthreads();

#pragma unroll
        for (int kk = 0; kk < 64; kk++) {
            float4 vv = *(const float4*)&Vs[kk * 64 + tx * 4];
            float v0 = vv.x, v1 = vv.y, v2 = vv.z, v3 = vv.w;
#pragma unroll
            for (int i = 0; i < 4; i++) {
                float p = Ps[(ty * 4 + i) * PS_STRIDE + kk];
                o_acc[i][0] = fmaf(p, v0, o_acc[i][0]);
                o_acc[i][1] = fmaf(p, v1, o_acc[i][1]);
                o_acc[i][2] = fmaf(p, v2, o_acc[i][2]);
                o_acc[i][3] = fmaf(p, v3, o_acc[i][3]);
            }
        }
    }

#pragma unroll
    for (int i = 0; i < 4; i++) {
        float inv = 1.f / l_i[i];
        int n = b * S_ + q0 + ty * 4 + i;
        float4 o4;
        o4.x = o_acc[i][0] * inv;
        o4.y = o_acc[i][1] * inv;
        o4.z = o_acc[i][2] * inv;
        o4.w = o_acc[i][3] * inv;
        *(float4*)(O + (size_t)n * D_ + h * 64 + tx * 4) = o4;
    }
}

// ---------------------------------------------------------------------------
extern "C" void kernel_launch(void* const* d_in, const int* in_sizes, int n_in,
                              void* d_out, int out_size)
{
    const float* x  = (const float*)d_in[0];
    const float* Wq = (const float*)d_in[1];
    const float* bq = (const float*)d_in[2];
    const float* Wk = (const float*)d_in[3];
    const float* bk = (const float*)d_in[4];
    const float* Wv = (const float*)d_in[5];
    const float* bv = (const float*)d_in[6];
    const float* Wo = (const float*)d_in[7];
    const float* bo = (const float*)d_in[8];
    float* out = (float*)d_out;

    float *qp, *kp, *vp, *op;
    cudaGetSymbolAddress((void**)&qp, g_q);
    cudaGetSymbolAddress((void**)&kp, g_k);
    cudaGetSymbolAddress((void**)&vp, g_v);
    cudaGetSymbolAddress((void**)&op, g_o);

    cudaFuncSetAttribute(gemm_mma_kernel,
                         cudaFuncAttributeMaxDynamicSharedMemorySize, GEMM_SMEM);
    const int attn_smem = (64*QS_STRIDE + 64*KS_STRIDE + 64*64 + 64*PS_STRIDE) * 4;
    cudaFuncSetAttribute(attn_kernel,
                         cudaFuncAttributeMaxDynamicSharedMemorySize, attn_smem);

    dim3 ggrid(D_ / TN, N_ / TM);   // (8, 32)

    gemm_mma_kernel<<<ggrid, 256, GEMM_SMEM>>>(x, Wq, bq, qp);
    gemm_mma_kernel<<<ggrid, 256, GEMM_SMEM>>>(x, Wk, bk, kp);
    gemm_mma_kernel<<<ggrid, 256, GEMM_SMEM>>>(x, Wv, bv, vp);

    attn_kernel<<<dim3(S_ / 64, B_ * H_), dim3(16, 16), attn_smem>>>(qp, kp, vp, op);

    gemm_mma_kernel<<<ggrid, 256, GEMM_SMEM>>>(op, Wo, bo, out);
}

// round 4
// speedup vs baseline: 3.4489x; 2.0894x over previous
#include <cuda_runtime.h>
#include <cuda_bf16.h>
#include <stdint.h>
#include <math.h>

#define B_  2
#define S_  2048
#define D_  1024
#define H_  16
#define HD_ 64
#define N_  (B_*S_)   // 4096

// Scratch (allocation-free rule: __device__ globals)
__device__ float g_q[N_*D_];
__device__ float g_k[N_*D_];
__device__ float g_v[N_*D_];
__device__ float g_o[N_*D_];

// ---------------------------------------------------------------------------
// Base-PTX helpers (no tcgen05: harness PTX target is non-'a' sm_103)
// ---------------------------------------------------------------------------
__device__ __forceinline__ void cp16(uint32_t dst, const void* src) {
    asm volatile("cp.async.cg.shared.global [%0], [%1], 16;"
                 :: "r"(dst), "l"(__cvta_generic_to_global(src)));
}
__device__ __forceinline__ void cp_commit() {
    asm volatile("cp.async.commit_group;");
}
template<int N> __device__ __forceinline__ void cp_wait() {
    asm volatile("cp.async.wait_group %0;" :: "n"(N));
}
__device__ __forceinline__ uint32_t f2tf32(float f) {
    uint32_t r;
    asm("cvt.rna.tf32.f32 %0, %1;" : "=r"(r) : "f"(f));
    return r;
}
__device__ __forceinline__ void mma_tf32(float c[4],
                                         const uint32_t a[4],
                                         const uint32_t b[2]) {
    asm volatile(
        "mma.sync.aligned.m16n8k8.row.col.f32.tf32.tf32.f32 "
        "{%0,%1,%2,%3}, {%4,%5,%6,%7}, {%8,%9}, {%0,%1,%2,%3};"
        : "+f"(c[0]), "+f"(c[1]), "+f"(c[2]), "+f"(c[3])
        : "r"(a[0]), "r"(a[1]), "r"(a[2]), "r"(a[3]),
          "r"(b[0]), "r"(b[1]));
}

// ---------------------------------------------------------------------------
// tf32 tensor-core GEMM: C[N_,1024] = A[N_,1024] @ W[1024,1024]^T + bias
// (unchanged from round 3: 128x128 CTA tile, 8 warps, 2-stage cp.async)
// ---------------------------------------------------------------------------
#define TM 128
#define TN 128
#define KC 32
#define NCH (D_/KC)
#define STG 2
#define ASTR 36
#define TILE_FLOATS (TM*ASTR)
#define STAGE_FLOATS (2*TILE_FLOATS)
#define GEMM_SMEM (STG*STAGE_FLOATS*4)

__device__ __forceinline__ void load_chunk(const float* __restrict__ A,
                                           const float* __restrict__ W,
                                           int row0, int col0, int c,
                                           float* stage, int tid)
{
    const uint32_t abase = (uint32_t)__cvta_generic_to_shared(stage);
    const uint32_t bbase = (uint32_t)__cvta_generic_to_shared(stage + TILE_FLOATS);
    const char* asrc = (const char*)(A + (size_t)row0 * D_ + c * KC);
    const char* bsrc = (const char*)(W + (size_t)col0 * D_ + c * KC);
#pragma unroll
    for (int i = 0; i < 4; i++) {
        int idx = tid + (i << 8);
        int r = idx >> 3, c16 = idx & 7;
        cp16(abase + (uint32_t)(r * (ASTR*4) + c16 * 16),
             asrc + (size_t)r * (D_*4) + c16 * 16);
    }
#pragma unroll
    for (int i = 0; i < 4; i++) {
        int idx = tid + (i << 8);
        int r = idx >> 3, c16 = idx & 7;
        cp16(bbase + (uint32_t)(r * (ASTR*4) + c16 * 16),
             bsrc + (size_t)r * (D_*4) + c16 * 16);
    }
    cp_commit();
}

__global__ __launch_bounds__(256, 2)
void gemm_mma_kernel(const float* __restrict__ A,
                     const float* __restrict__ W,
                     const float* __restrict__ bias,
                     float* __restrict__ C)
{
    extern __shared__ float sm[];
    const int tid  = threadIdx.x;
    const int lane = tid & 31;
    const int warp = tid >> 5;
    const int wm   = warp & 3;
    const int wn   = warp >> 2;
    const int row0 = blockIdx.y * TM;
    const int col0 = blockIdx.x * TN;

    const int lr = lane >> 2;
    const int lc = lane & 3;

    float c_f[2][8][4];
#pragma unroll
    for (int mi = 0; mi < 2; mi++)
#pragma unroll
        for (int ni = 0; ni < 8; ni++)
#pragma unroll
            for (int j = 0; j < 4; j++) c_f[mi][ni][j] = 0.f;

    load_chunk(A, W, row0, col0, 0, sm, tid);
    load_chunk(A, W, row0, col0, 1, sm + STAGE_FLOATS, tid);

    for (int kt = 0; kt < NCH; kt++) {
        if (kt >= NCH - 1) cp_wait<0>(); else cp_wait<1>();
        __syncthreads();

        const float* As = sm + (kt & 1) * STAGE_FLOATS;
        const float* Bs = As + TILE_FLOATS;

#pragma unroll
        for (int ks = 0; ks < 4; ks++) {
            const int k0 = ks * 8 + lc;
            uint32_t a_f[2][4];
#pragma unroll
            for (int mi = 0; mi < 2; mi++) {
                int r = wm * 32 + mi * 16 + lr;
                a_f[mi][0] = f2tf32(As[r * ASTR + k0]);
                a_f[mi][1] = f2tf32(As[(r + 8) * ASTR + k0]);
                a_f[mi][2] = f2tf32(As[r * ASTR + k0 + 4]);
                a_f[mi][3] = f2tf32(As[(r + 8) * ASTR + k0 + 4]);
            }
            uint32_t b_f[8][2];
#pragma unroll
            for (int ni = 0; ni < 8; ni++) {
                int n = wn * 64 + ni * 8 + lr;
                b_f[ni][0] = f2tf32(Bs[n * ASTR + k0]);
                b_f[ni][1] = f2tf32(Bs[n * ASTR + k0 + 4]);
            }
#pragma unroll
            for (int mi = 0; mi < 2; mi++)
#pragma unroll
                for (int ni = 0; ni < 8; ni++)
                    mma_tf32(c_f[mi][ni], a_f[mi], b_f[ni]);
        }
        __syncthreads();

        if (kt + STG < NCH)
            load_chunk(A, W, row0, col0, kt + STG,
                       sm + (kt & 1) * STAGE_FLOATS, tid);
    }

#pragma unroll
    for (int ni = 0; ni < 8; ni++) {
        int col = col0 + wn * 64 + ni * 8 + lc * 2;
        float2 bb = *(const float2*)(bias + col);
#pragma unroll
        for (int mi = 0; mi < 2; mi++) {
            int r = row0 + wm * 32 + mi * 16 + lr;
            float2 o0, o1;
            o0.x = c_f[mi][ni][0] + bb.x;
            o0.y = c_f[mi][ni][1] + bb.y;
            o1.x = c_f[mi][ni][2] + bb.x;
            o1.y = c_f[mi][ni][3] + bb.y;
            *(float2*)(C + (size_t)r * D_ + col)       = o0;
            *(float2*)(C + (size_t)(r + 8) * D_ + col) = o1;
        }
    }
}

// ---------------------------------------------------------------------------
// Flash attention with tf32 mma.sync.
// CTA: 128 Q rows x one (b,h). 8 warps, each m16 x full n64.
// Smem (floats): Qs[128*68] | stage{0,1}: Ks[64*68], Vs[64*72]
// ---------------------------------------------------------------------------
#define AQ_STR 68
#define AK_STR 68
#define AV_STR 72
#define AQ_FLOATS (128*AQ_STR)              // 8704
#define AK_FLOATS (64*AK_STR)               // 4352
#define AV_FLOATS (64*AV_STR)               // 4608
#define ASTAGE_FLOATS (AK_FLOATS+AV_FLOATS) // 8960
#define ATTN_SMEM ((AQ_FLOATS + 2*ASTAGE_FLOATS)*4)  // 106496 bytes

__device__ __forceinline__ void attn_load_kv(const float* __restrict__ kg,
                                             const float* __restrict__ vg,
                                             int kt, float* stage, int tid)
{
    const uint32_t kb = (uint32_t)__cvta_generic_to_shared(stage);
    const uint32_t vb = (uint32_t)__cvta_generic_to_shared(stage + AK_FLOATS);
    const char* ksrc = (const char*)(kg + (size_t)kt * 64 * D_);
    const char* vsrc = (const char*)(vg + (size_t)kt * 64 * D_);
#pragma unroll
    for (int i = 0; i < 4; i++) {           // 64 rows x 64 floats (16 x 16B)
        int idx = tid + (i << 8);
        int r = idx >> 4, c16 = idx & 15;
        cp16(kb + (uint32_t)(r * (AK_STR*4) + c16 * 16),
             ksrc + (size_t)r * (D_*4) + c16 * 16);
    }
#pragma unroll
    for (int i = 0; i < 4; i++) {
        int idx = tid + (i << 8);
        int r = idx >> 4, c16 = idx & 15;
        cp16(vb + (uint32_t)(r * (AV_STR*4) + c16 * 16),
             vsrc + (size_t)r * (D_*4) + c16 * 16);
    }
    cp_commit();
}

__global__ __launch_bounds__(256, 1)
void attn_mma_kernel(const float* __restrict__ Q,
                     const float* __restrict__ Kg,
                     const float* __restrict__ Vg,
                     float* __restrict__ O)
{
    extern __shared__ float sm[];
    const int tid  = threadIdx.x;
    const int lane = tid & 31;
    const int warp = tid >> 5;
    const int gr   = lane >> 2;   // 0..7 (row in group)
    const int lc   = lane & 3;    // 0..3

    const int q0 = blockIdx.x * 128;
    const int bh = blockIdx.y;
    const int b  = bh >> 4;
    const int h  = bh & 15;

    const float* qg = Q  + ((size_t)(b * S_ + q0)) * D_ + h * HD_;
    const float* kg = Kg + ((size_t)b * S_) * D_ + h * HD_;
    const float* vg = Vg + ((size_t)b * S_) * D_ + h * HD_;

    // --- Q tile -> smem (2048 cp16), grouped with KV block 0 ---
    {
        const uint32_t qb = (uint32_t)__cvta_generic_to_shared(sm);
        const char* qsrc = (const char*)qg;
#pragma unroll
        for (int i = 0; i < 8; i++) {       // 128 rows x 64 floats
            int idx = tid + (i << 8);
            int r = idx >> 4, c16 = idx & 15;
            cp16(qb + (uint32_t)(r * (AQ_STR*4) + c16 * 16),
                 qsrc + (size_t)r * (D_*4) + c16 * 16);
        }
    }
    attn_load_kv(kg, vg, 0, sm + AQ_FLOATS, tid);                  // group 0 (Q+KV0)
    attn_load_kv(kg, vg, 1, sm + AQ_FLOATS + ASTAGE_FLOATS, tid);  // group 1

    uint32_t qf[8][4];
    float co[8][4];
#pragma unroll
    for (int ni = 0; ni < 8; ni++)
#pragma unroll
        for (int j = 0; j < 4; j++) co[ni][j] = 0.f;
    float m0 = -1e30f, m1 = -1e30f, l0 = 0.f, l1 = 0.f;

    const int src  = (lane & ~3) | (lc >> 1);
    const int src2 = src + 2;
    const bool odd = (lc & 1);

    for (int kt = 0; kt < S_/64; kt++) {
        if (kt >= S_/64 - 1) cp_wait<0>(); else cp_wait<1>();
        __syncthreads();

        if (kt == 0) {
            // Q fragments (scaled by 1/sqrt(64)), persistent in registers
            const float scale = 0.125f;
            const float* Qs = sm;
            const int r = warp * 16 + gr;
#pragma unroll
            for (int ks = 0; ks < 8; ks++) {
                const int k0 = ks * 8 + lc;
                qf[ks][0] = f2tf32(Qs[r * AQ_STR + k0] * scale);
                qf[ks][1] = f2tf32(Qs[(r + 8) * AQ_STR + k0] * scale);
                qf[ks][2] = f2tf32(Qs[r * AQ_STR + k0 + 4] * scale);
                qf[ks][3] = f2tf32(Qs[(r + 8) * AQ_STR + k0 + 4] * scale);
            }
        }

        const float* Ks = sm + AQ_FLOATS + (kt & 1) * ASTAGE_FLOATS;
        const float* Vs = Ks + AK_FLOATS;

        // --- S = (scaled Q) @ K^T : 16 x 64 per warp ---
        float c[8][4];
#pragma unroll
        for (int ni = 0; ni < 8; ni++)
#pragma unroll
            for (int j = 0; j < 4; j++) c[ni][j] = 0.f;

#pragma unroll
        for (int ks = 0; ks < 8; ks++) {
            const int k0 = ks * 8 + lc;
#pragma unroll
            for (int ni = 0; ni < 8; ni++) {
                uint32_t bfr[2];
                const int n = ni * 8 + gr;
                bfr[0] = f2tf32(Ks[n * AK_STR + k0]);
                bfr[1] = f2tf32(Ks[n * AK_STR + k0 + 4]);
                mma_tf32(c[ni], qf[ks], bfr);
            }
        }

        // --- online softmax (rows gr, gr+8; 4-lane group reductions) ---
        float mt0 = fmaxf(c[0][0], c[0][1]);
        float mt1 = fmaxf(c[0][2], c[0][3]);
#pragma unroll
        for (int ni = 1; ni < 8; ni++) {
            mt0 = fmaxf(mt0, fmaxf(c[ni][0], c[ni][1]));
            mt1 = fmaxf(mt1, fmaxf(c[ni][2], c[ni][3]));
        }
        mt0 = fmaxf(mt0, __shfl_xor_sync(0xffffffffu, mt0, 1));
        mt0 = fmaxf(mt0, __shfl_xor_sync(0xffffffffu, mt0, 2));
        mt1 = fmaxf(mt1, __shfl_xor_sync(0xffffffffu, mt1, 1));
        mt1 = fmaxf(mt1, __shfl_xor_sync(0xffffffffu, mt1, 2));

        const float mn0 = fmaxf(m0, mt0);
        const float mn1 = fmaxf(m1, mt1);
        const float al0 = __expf(m0 - mn0);
        const float al1 = __expf(m1 - mn1);

        float rs0 = 0.f, rs1 = 0.f;
#pragma unroll
        for (int ni = 0; ni < 8; ni++) {
            c[ni][0] = __expf(c[ni][0] - mn0); rs0 += c[ni][0];
            c[ni][1] = __expf(c[ni][1] - mn0); rs0 += c[ni][1];
            c[ni][2] = __expf(c[ni][2] - mn1); rs1 += c[ni][2];
            c[ni][3] = __expf(c[ni][3] - mn1); rs1 += c[ni][3];
        }
        rs0 += __shfl_xor_sync(0xffffffffu, rs0, 1);
        rs0 += __shfl_xor_sync(0xffffffffu, rs0, 2);
        rs1 += __shfl_xor_sync(0xffffffffu, rs1, 1);
        rs1 += __shfl_xor_sync(0xffffffffu, rs1, 2);

        l0 = l0 * al0 + rs0;  m0 = mn0;
        l1 = l1 * al1 + rs1;  m1 = mn1;

#pragma unroll
        for (int ni = 0; ni < 8; ni++) {
            co[ni][0] *= al0; co[ni][1] *= al0;
            co[ni][2] *= al1; co[ni][3] *= al1;
        }

        // --- O += P @ V ---
#pragma unroll
        for (int ks = 0; ks < 8; ks++) {
            // P accumulator fragment -> A fragment (shuffle transpose within group)
            float t0 = __shfl_sync(0xffffffffu, c[ks][0], src);
            float t1 = __shfl_sync(0xffffffffu, c[ks][1], src);
            float t2 = __shfl_sync(0xffffffffu, c[ks][2], src);
            float t3 = __shfl_sync(0xffffffffu, c[ks][3], src);
            float u0 = __shfl_sync(0xffffffffu, c[ks][0], src2);
            float u1 = __shfl_sync(0xffffffffu, c[ks][1], src2);
            float u2 = __shfl_sync(0xffffffffu, c[ks][2], src2);
            float u3 = __shfl_sync(0xffffffffu, c[ks][3], src2);
            uint32_t af[4];
            af[0] = f2tf32(odd ? t1 : t0);
            af[1] = f2tf32(odd ? t3 : t2);
            af[2] = f2tf32(odd ? u1 : u0);
            af[3] = f2tf32(odd ? u3 : u2);

            const int kp0 = ks * 8 + lc;
#pragma unroll
            for (int ni = 0; ni < 8; ni++) {
                uint32_t bfr[2];
                const int n = ni * 8 + gr;
                bfr[0] = f2tf32(Vs[kp0 * AV_STR + n]);
                bfr[1] = f2tf32(Vs[(kp0 + 4) * AV_STR + n]);
                mma_tf32(co[ni], af, bfr);
            }
        }

        __syncthreads();
        if (kt + 2 < S_/64)
            attn_load_kv(kg, vg, kt + 2,
                         sm + AQ_FLOATS + (kt & 1) * ASTAGE_FLOATS, tid);
    }

    // --- finalize: O /= l, store to [N, D] merged-head layout ---
    const float inv0 = 1.f / l0;
    const float inv1 = 1.f / l1;
    const int n0 = b * S_ + q0 + warp * 16 + gr;
#pragma unroll
    for (int ni = 0; ni < 8; ni++) {
        const int col = h * HD_ + ni * 8 + lc * 2;
        float2 o0, o1;
        o0.x = co[ni][0] * inv0; o0.y = co[ni][1] * inv0;
        o1.x = co[ni][2] * inv1; o1.y = co[ni][3] * inv1;
        *(float2*)(O + (size_t)n0 * D_ + col)       = o0;
        *(float2*)(O + (size_t)(n0 + 8) * D_ + col) = o1;
    }
}

// ---------------------------------------------------------------------------
extern "C" void kernel_launch(void* const* d_in, const int* in_sizes, int n_in,
                              void* d_out, int out_size)
{
    const float* x  = (const float*)d_in[0];
    const float* Wq = (const float*)d_in[1];
    const float* bq = (const float*)d_in[2];
    const float* Wk = (const float*)d_in[3];
    const float* bk = (const float*)d_in[4];
    const float* Wv = (const float*)d_in[5];
    const float* bv = (const float*)d_in[6];
    const float* Wo = (const float*)d_in[7];
    const float* bo = (const float*)d_in[8];
    float* out = (float*)d_out;

    float *qp, *kp, *vp, *op;
    cudaGetSymbolAddress((void**)&qp, g_q);
    cudaGetSymbolAddress((void**)&kp, g_k);
    cudaGetSymbolAddress((void**)&vp, g_v);
    cudaGetSymbolAddress((void**)&op, g_o);

    cudaFuncSetAttribute(gemm_mma_kernel,
                         cudaFuncAttributeMaxDynamicSharedMemorySize, GEMM_SMEM);
    cudaFuncSetAttribute(attn_mma_kernel,
                         cudaFuncAttributeMaxDynamicSharedMemorySize, ATTN_SMEM);

    dim3 ggrid(D_ / TN, N_ / TM);   // (8, 32)

    gemm_mma_kernel<<<ggrid, 256, GEMM_SMEM>>>(x, Wq, bq, qp);
    gemm_mma_kernel<<<ggrid, 256, GEMM_SMEM>>>(x, Wk, bk, kp);
    gemm_mma_kernel<<<ggrid, 256, GEMM_SMEM>>>(x, Wv, bv, vp);

    attn_mma_kernel<<<dim3(S_ / 128, B_ * H_), 256, ATTN_SMEM>>>(qp, kp, vp, op);

    gemm_mma_kernel<<<ggrid, 256, GEMM_SMEM>>>(op, Wo, bo, out);
}

// round 5
// speedup vs baseline: 3.6730x; 1.0650x over previous
#include <cuda_runtime.h>
#include <cuda_bf16.h>
#include <stdint.h>
#include <math.h>

#define B_  2
#define S_  2048
#define D_  1024
#define H_  16
#define HD_ 64
#define N_  (B_*S_)   // 4096

// Scratch (allocation-free rule: __device__ globals)
__device__ float g_q[N_*D_];
__device__ float g_k[N_*D_];
__device__ float g_v[N_*D_];
__device__ float g_o[N_*D_];
__device__ float g_xr[N_*D_];   // tf32-rounded x
__device__ float g_wr[D_*D_];   // tf32-rounded W (reused per projection)

// ---------------------------------------------------------------------------
// Base-PTX helpers (no tcgen05: harness PTX target is non-'a' sm_103)
// ---------------------------------------------------------------------------
__device__ __forceinline__ void cp16(uint32_t dst, const void* src) {
    asm volatile("cp.async.cg.shared.global [%0], [%1], 16;"
                 :: "r"(dst), "l"(__cvta_generic_to_global(src)));
}
__device__ __forceinline__ void cp_commit() {
    asm volatile("cp.async.commit_group;");
}
template<int N> __device__ __forceinline__ void cp_wait() {
    asm volatile("cp.async.wait_group %0;" :: "n"(N));
}
__device__ __forceinline__ uint32_t f2tf32(float f) {
    uint32_t r;
    asm("cvt.rna.tf32.f32 %0, %1;" : "=r"(r) : "f"(f));
    return r;
}
__device__ __forceinline__ void mma_tf32(float c[4],
                                         const uint32_t a[4],
                                         const uint32_t b[2]) {
    asm volatile(
        "mma.sync.aligned.m16n8k8.row.col.f32.tf32.tf32.f32 "
        "{%0,%1,%2,%3}, {%4,%5,%6,%7}, {%8,%9}, {%0,%1,%2,%3};"
        : "+f"(c[0]), "+f"(c[1]), "+f"(c[2]), "+f"(c[3])
        : "r"(a[0]), "r"(a[1]), "r"(a[2]), "r"(a[3]),
          "r"(b[0]), "r"(b[1]));
}

// ---------------------------------------------------------------------------
// Prepass: fp32 -> tf32-rounded fp32 bits (one pass per tensor)
// ---------------------------------------------------------------------------
__global__ __launch_bounds__(256)
void round_tf32_kernel(const float* __restrict__ in, float* __restrict__ out, int n4) {
    int i = blockIdx.x * blockDim.x + threadIdx.x;
    if (i < n4) {
        float4 v = ((const float4*)in)[i];
        float4 o;
        o.x = __uint_as_float(f2tf32(v.x));
        o.y = __uint_as_float(f2tf32(v.y));
        o.z = __uint_as_float(f2tf32(v.z));
        o.w = __uint_as_float(f2tf32(v.w));
        ((float4*)out)[i] = o;
    }
}

// ---------------------------------------------------------------------------
// tf32 tensor-core GEMM: C = A[N_,1024] @ W[1024,1024]^T + bias.
// Inputs are PRE-ROUNDED tf32 bits -> fragments loaded as raw uint32, no cvt.
// ROUND_OUT=1: epilogue rounds outputs to tf32 (for Q/K/V feeding attention).
// ---------------------------------------------------------------------------
#define TM 128
#define TN 128
#define KC 32
#define NCH (D_/KC)
#define STG 2
#define ASTR 36
#define TILE_FLOATS (TM*ASTR)
#define STAGE_FLOATS (2*TILE_FLOATS)
#define GEMM_SMEM (STG*STAGE_FLOATS*4)

__device__ __forceinline__ void load_chunk(const float* __restrict__ A,
                                           const float* __restrict__ W,
                                           int row0, int col0, int c,
                                           float* stage, int tid)
{
    const uint32_t abase = (uint32_t)__cvta_generic_to_shared(stage);
    const uint32_t bbase = (uint32_t)__cvta_generic_to_shared(stage + TILE_FLOATS);
    const char* asrc = (const char*)(A + (size_t)row0 * D_ + c * KC);
    const char* bsrc = (const char*)(W + (size_t)col0 * D_ + c * KC);
#pragma unroll
    for (int i = 0; i < 4; i++) {
        int idx = tid + (i << 8);
        int r = idx >> 3, c16 = idx & 7;
        cp16(abase + (uint32_t)(r * (ASTR*4) + c16 * 16),
             asrc + (size_t)r * (D_*4) + c16 * 16);
    }
#pragma unroll
    for (int i = 0; i < 4; i++) {
        int idx = tid + (i << 8);
        int r = idx >> 3, c16 = idx & 7;
        cp16(bbase + (uint32_t)(r * (ASTR*4) + c16 * 16),
             bsrc + (size_t)r * (D_*4) + c16 * 16);
    }
    cp_commit();
}

template<int ROUND_OUT>
__global__ __launch_bounds__(256, 2)
void gemm_mma_kernel(const float* __restrict__ A,
                     const float* __restrict__ W,
                     const float* __restrict__ bias,
                     float* __restrict__ C)
{
    extern __shared__ float sm[];
    const int tid  = threadIdx.x;
    const int lane = tid & 31;
    const int warp = tid >> 5;
    const int wm   = warp & 3;
    const int wn   = warp >> 2;
    const int row0 = blockIdx.y * TM;
    const int col0 = blockIdx.x * TN;

    const int lr = lane >> 2;
    const int lc = lane & 3;

    float c_f[2][8][4];
#pragma unroll
    for (int mi = 0; mi < 2; mi++)
#pragma unroll
        for (int ni = 0; ni < 8; ni++)
#pragma unroll
            for (int j = 0; j < 4; j++) c_f[mi][ni][j] = 0.f;

    load_chunk(A, W, row0, col0, 0, sm, tid);
    load_chunk(A, W, row0, col0, 1, sm + STAGE_FLOATS, tid);

    for (int kt = 0; kt < NCH; kt++) {
        if (kt >= NCH - 1) cp_wait<0>(); else cp_wait<1>();
        __syncthreads();

        const uint32_t* As = (const uint32_t*)(sm + (kt & 1) * STAGE_FLOATS);
        const uint32_t* Bs = As + TILE_FLOATS;

#pragma unroll
        for (int ks = 0; ks < 4; ks++) {
            const int k0 = ks * 8 + lc;
            uint32_t a_f[2][4];
#pragma unroll
            for (int mi = 0; mi < 2; mi++) {
                int r = wm * 32 + mi * 16 + lr;
                a_f[mi][0] = As[r * ASTR + k0];
                a_f[mi][1] = As[(r + 8) * ASTR + k0];
                a_f[mi][2] = As[r * ASTR + k0 + 4];
                a_f[mi][3] = As[(r + 8) * ASTR + k0 + 4];
            }
            uint32_t b_f[8][2];
#pragma unroll
            for (int ni = 0; ni < 8; ni++) {
                int n = wn * 64 + ni * 8 + lr;
                b_f[ni][0] = Bs[n * ASTR + k0];
                b_f[ni][1] = Bs[n * ASTR + k0 + 4];
            }
#pragma unroll
            for (int mi = 0; mi < 2; mi++)
#pragma unroll
                for (int ni = 0; ni < 8; ni++)
                    mma_tf32(c_f[mi][ni], a_f[mi], b_f[ni]);
        }
        __syncthreads();

        if (kt + STG < NCH)
            load_chunk(A, W, row0, col0, kt + STG,
                       sm + (kt & 1) * STAGE_FLOATS, tid);
    }

#pragma unroll
    for (int ni = 0; ni < 8; ni++) {
        int col = col0 + wn * 64 + ni * 8 + lc * 2;
        float2 bb = *(const float2*)(bias + col);
#pragma unroll
        for (int mi = 0; mi < 2; mi++) {
            int r = row0 + wm * 32 + mi * 16 + lr;
            float2 o0, o1;
            o0.x = c_f[mi][ni][0] + bb.x;
            o0.y = c_f[mi][ni][1] + bb.y;
            o1.x = c_f[mi][ni][2] + bb.x;
            o1.y = c_f[mi][ni][3] + bb.y;
            if (ROUND_OUT) {
                o0.x = __uint_as_float(f2tf32(o0.x));
                o0.y = __uint_as_float(f2tf32(o0.y));
                o1.x = __uint_as_float(f2tf32(o1.x));
                o1.y = __uint_as_float(f2tf32(o1.y));
            }
            *(float2*)(C + (size_t)r * D_ + col)       = o0;
            *(float2*)(C + (size_t)(r + 8) * D_ + col) = o1;
        }
    }
}

// ---------------------------------------------------------------------------
// Flash attention with tf32 mma.sync; Q/K/V pre-rounded to tf32 pattern,
// so K/V/Q fragments are raw bit loads (no cvt). Only P needs cvt.
// ---------------------------------------------------------------------------
#define AQ_STR 68
#define AK_STR 68
#define AV_STR 72
#define AQ_FLOATS (128*AQ_STR)
#define AK_FLOATS (64*AK_STR)
#define AV_FLOATS (64*AV_STR)
#define ASTAGE_FLOATS (AK_FLOATS+AV_FLOATS)
#define ATTN_SMEM ((AQ_FLOATS + 2*ASTAGE_FLOATS)*4)

__device__ __forceinline__ void attn_load_kv(const float* __restrict__ kg,
                                             const float* __restrict__ vg,
                                             int kt, float* stage, int tid)
{
    const uint32_t kb = (uint32_t)__cvta_generic_to_shared(stage);
    const uint32_t vb = (uint32_t)__cvta_generic_to_shared(stage + AK_FLOATS);
    const char* ksrc = (const char*)(kg + (size_t)kt * 64 * D_);
    const char* vsrc = (const char*)(vg + (size_t)kt * 64 * D_);
#pragma unroll
    for (int i = 0; i < 4; i++) {
        int idx = tid + (i << 8);
        int r = idx >> 4, c16 = idx & 15;
        cp16(kb + (uint32_t)(r * (AK_STR*4) + c16 * 16),
             ksrc + (size_t)r * (D_*4) + c16 * 16);
    }
#pragma unroll
    for (int i = 0; i < 4; i++) {
        int idx = tid + (i << 8);
        int r = idx >> 4, c16 = idx & 15;
        cp16(vb + (uint32_t)(r * (AV_STR*4) + c16 * 16),
             vsrc + (size_t)r * (D_*4) + c16 * 16);
    }
    cp_commit();
}

__global__ __launch_bounds__(256, 1)
void attn_mma_kernel(const float* __restrict__ Q,
                     const float* __restrict__ Kg,
                     const float* __restrict__ Vg,
                     float* __restrict__ O)
{
    extern __shared__ float sm[];
    const int tid  = threadIdx.x;
    const int lane = tid & 31;
    const int warp = tid >> 5;
    const int gr   = lane >> 2;
    const int lc   = lane & 3;

    const int q0 = blockIdx.x * 128;
    const int bh = blockIdx.y;
    const int b  = bh >> 4;
    const int h  = bh & 15;

    const float* qg = Q  + ((size_t)(b * S_ + q0)) * D_ + h * HD_;
    const float* kg = Kg + ((size_t)b * S_) * D_ + h * HD_;
    const float* vg = Vg + ((size_t)b * S_) * D_ + h * HD_;

    {
        const uint32_t qb = (uint32_t)__cvta_generic_to_shared(sm);
        const char* qsrc = (const char*)qg;
#pragma unroll
        for (int i = 0; i < 8; i++) {
            int idx = tid + (i << 8);
            int r = idx >> 4, c16 = idx & 15;
            cp16(qb + (uint32_t)(r * (AQ_STR*4) + c16 * 16),
                 qsrc + (size_t)r * (D_*4) + c16 * 16);
        }
    }
    attn_load_kv(kg, vg, 0, sm + AQ_FLOATS, tid);
    attn_load_kv(kg, vg, 1, sm + AQ_FLOATS + ASTAGE_FLOATS, tid);

    uint32_t qf[8][4];
    float co[8][4];
#pragma unroll
    for (int ni = 0; ni < 8; ni++)
#pragma unroll
        for (int j = 0; j < 4; j++) co[ni][j] = 0.f;
    float m0 = -1e30f, m1 = -1e30f, l0 = 0.f, l1 = 0.f;

    const int src  = (lane & ~3) | (lc >> 1);
    const int src2 = src + 2;
    const bool odd = (lc & 1);

    for (int kt = 0; kt < S_/64; kt++) {
        if (kt >= S_/64 - 1) cp_wait<0>(); else cp_wait<1>();
        __syncthreads();

        if (kt == 0) {
            // Q pre-rounded to tf32 pattern; *0.125f (2^-3) preserves it.
            const float scale = 0.125f;
            const float* Qs = sm;
            const int r = warp * 16 + gr;
#pragma unroll
            for (int ks = 0; ks < 8; ks++) {
                const int k0 = ks * 8 + lc;
                qf[ks][0] = __float_as_uint(Qs[r * AQ_STR + k0] * scale);
                qf[ks][1] = __float_as_uint(Qs[(r + 8) * AQ_STR + k0] * scale);
                qf[ks][2] = __float_as_uint(Qs[r * AQ_STR + k0 + 4] * scale);
                qf[ks][3] = __float_as_uint(Qs[(r + 8) * AQ_STR + k0 + 4] * scale);
            }
        }

        const uint32_t* Ks = (const uint32_t*)(sm + AQ_FLOATS + (kt & 1) * ASTAGE_FLOATS);
        const uint32_t* Vs = Ks + AK_FLOATS;

        // --- S = (scaled Q) @ K^T ---
        float c[8][4];
#pragma unroll
        for (int ni = 0; ni < 8; ni++)
#pragma unroll
            for (int j = 0; j < 4; j++) c[ni][j] = 0.f;

#pragma unroll
        for (int ks = 0; ks < 8; ks++) {
            const int k0 = ks * 8 + lc;
#pragma unroll
            for (int ni = 0; ni < 8; ni++) {
                uint32_t bfr[2];
                const int n = ni * 8 + gr;
                bfr[0] = Ks[n * AK_STR + k0];
                bfr[1] = Ks[n * AK_STR + k0 + 4];
                mma_tf32(c[ni], qf[ks], bfr);
            }
        }

        // --- online softmax ---
        float mt0 = fmaxf(c[0][0], c[0][1]);
        float mt1 = fmaxf(c[0][2], c[0][3]);
#pragma unroll
        for (int ni = 1; ni < 8; ni++) {
            mt0 = fmaxf(mt0, fmaxf(c[ni][0], c[ni][1]));
            mt1 = fmaxf(mt1, fmaxf(c[ni][2], c[ni][3]));
        }
        mt0 = fmaxf(mt0, __shfl_xor_sync(0xffffffffu, mt0, 1));
        mt0 = fmaxf(mt0, __shfl_xor_sync(0xffffffffu, mt0, 2));
        mt1 = fmaxf(mt1, __shfl_xor_sync(0xffffffffu, mt1, 1));
        mt1 = fmaxf(mt1, __shfl_xor_sync(0xffffffffu, mt1, 2));

        const float mn0 = fmaxf(m0, mt0);
        const float mn1 = fmaxf(m1, mt1);
        const float al0 = __expf(m0 - mn0);
        const float al1 = __expf(m1 - mn1);

        float rs0 = 0.f, rs1 = 0.f;
#pragma unroll
        for (int ni = 0; ni < 8; ni++) {
            c[ni][0] = __expf(c[ni][0] - mn0); rs0 += c[ni][0];
            c[ni][1] = __expf(c[ni][1] - mn0); rs0 += c[ni][1];
            c[ni][2] = __expf(c[ni][2] - mn1); rs1 += c[ni][2];
            c[ni][3] = __expf(c[ni][3] - mn1); rs1 += c[ni][3];
        }
        rs0 += __shfl_xor_sync(0xffffffffu, rs0, 1);
        rs0 += __shfl_xor_sync(0xffffffffu, rs0, 2);
        rs1 += __shfl_xor_sync(0xffffffffu, rs1, 1);
        rs1 += __shfl_xor_sync(0xffffffffu, rs1, 2);

        l0 = l0 * al0 + rs0;  m0 = mn0;
        l1 = l1 * al1 + rs1;  m1 = mn1;

#pragma unroll
        for (int ni = 0; ni < 8; ni++) {
            co[ni][0] *= al0; co[ni][1] *= al0;
            co[ni][2] *= al1; co[ni][3] *= al1;
        }

        // --- O += P @ V ---
#pragma unroll
        for (int ks = 0; ks < 8; ks++) {
            float t0 = __shfl_sync(0xffffffffu, c[ks][0], src);
            float t1 = __shfl_sync(0xffffffffu, c[ks][1], src);
            float t2 = __shfl_sync(0xffffffffu, c[ks][2], src);
            float t3 = __shfl_sync(0xffffffffu, c[ks][3], src);
            float u0 = __shfl_sync(0xffffffffu, c[ks][0], src2);
            float u1 = __shfl_sync(0xffffffffu, c[ks][1], src2);
            float u2 = __shfl_sync(0xffffffffu, c[ks][2], src2);
            float u3 = __shfl_sync(0xffffffffu, c[ks][3], src2);
            uint32_t af[4];
            af[0] = f2tf32(odd ? t1 : t0);
            af[1] = f2tf32(odd ? t3 : t2);
            af[2] = f2tf32(odd ? u1 : u0);
            af[3] = f2tf32(odd ? u3 : u2);

            const int kp0 = ks * 8 + lc;
#pragma unroll
            for (int ni = 0; ni < 8; ni++) {
                uint32_t bfr[2];
                const int n = ni * 8 + gr;
                bfr[0] = Vs[kp0 * AV_STR + n];
                bfr[1] = Vs[(kp0 + 4) * AV_STR + n];
                mma_tf32(co[ni], af, bfr);
            }
        }

        __syncthreads();
        if (kt + 2 < S_/64)
            attn_load_kv(kg, vg, kt + 2,
                         sm + AQ_FLOATS + (kt & 1) * ASTAGE_FLOATS, tid);
    }

    // --- finalize: O /= l, tf32-round (final GEMM reads raw bits), store ---
    const float inv0 = 1.f / l0;
    const float inv1 = 1.f / l1;
    const int n0 = b * S_ + q0 + warp * 16 + gr;
#pragma unroll
    for (int ni = 0; ni < 8; ni++) {
        const int col = h * HD_ + ni * 8 + lc * 2;
        float2 o0, o1;
        o0.x = __uint_as_float(f2tf32(co[ni][0] * inv0));
        o0.y = __uint_as_float(f2tf32(co[ni][1] * inv0));
        o1.x = __uint_as_float(f2tf32(co[ni][2] * inv1));
        o1.y = __uint_as_float(f2tf32(co[ni][3] * inv1));
        *(float2*)(O + (size_t)n0 * D_ + col)       = o0;
        *(float2*)(O + (size_t)(n0 + 8) * D_ + col) = o1;
    }
}

// ---------------------------------------------------------------------------
extern "C" void kernel_launch(void* const* d_in, const int* in_sizes, int n_in,
                              void* d_out, int out_size)
{
    const float* x  = (const float*)d_in[0];
    const float* Wq = (const float*)d_in[1];
    const float* bq = (const float*)d_in[2];
    const float* Wk = (const float*)d_in[3];
    const float* bk = (const float*)d_in[4];
    const float* Wv = (const float*)d_in[5];
    const float* bv = (const float*)d_in[6];
    const float* Wo = (const float*)d_in[7];
    const float* bo = (const float*)d_in[8];
    float* out = (float*)d_out;

    float *qp, *kp, *vp, *op, *xr, *wr;
    cudaGetSymbolAddress((void**)&qp, g_q);
    cudaGetSymbolAddress((void**)&kp, g_k);
    cudaGetSymbolAddress((void**)&vp, g_v);
    cudaGetSymbolAddress((void**)&op, g_o);
    cudaGetSymbolAddress((void**)&xr, g_xr);
    cudaGetSymbolAddress((void**)&wr, g_wr);

    cudaFuncSetAttribute(gemm_mma_kernel<0>,
                         cudaFuncAttributeMaxDynamicSharedMemorySize, GEMM_SMEM);
    cudaFuncSetAttribute(gemm_mma_kernel<1>,
                         cudaFuncAttributeMaxDynamicSharedMemorySize, GEMM_SMEM);
    cudaFuncSetAttribute(attn_mma_kernel,
                         cudaFuncAttributeMaxDynamicSharedMemorySize, ATTN_SMEM);

    const int n4x = N_ * D_ / 4;
    const int n4w = D_ * D_ / 4;
    dim3 ggrid(D_ / TN, N_ / TM);

    round_tf32_kernel<<<n4x / 256, 256>>>(x, xr, n4x);
    round_tf32_kernel<<<n4w / 256, 256>>>(Wq, wr, n4w);
    gemm_mma_kernel<1><<<ggrid, 256, GEMM_SMEM>>>(xr, wr, bq, qp);
    round_tf32_kernel<<<n4w / 256, 256>>>(Wk, wr, n4w);
    gemm_mma_kernel<1><<<ggrid, 256, GEMM_SMEM>>>(xr, wr, bk, kp);
    round_tf32_kernel<<<n4w / 256, 256>>>(Wv, wr, n4w);
    gemm_mma_kernel<1><<<ggrid, 256, GEMM_SMEM>>>(xr, wr, bv, vp);

    attn_mma_kernel<<<dim3(S_ / 128, B_ * H_), 256, ATTN_SMEM>>>(qp, kp, vp, op);

    round_tf32_kernel<<<n4w / 256, 256>>>(Wo, wr, n4w);
    gemm_mma_kernel<0><<<ggrid, 256, GEMM_SMEM>>>(op, wr, bo, out);
}

// round 6
// speedup vs baseline: 3.9113x; 1.0649x over previous
#include <cuda_runtime.h>
#include <cuda_bf16.h>
#include <stdint.h>
#include <math.h>

#define B_  2
#define S_  2048
#define D_  1024
#define H_  16
#define HD_ 64
#define N_  (B_*S_)   // 4096

// Scratch (allocation-free rule: __device__ globals)
__device__ float g_q[N_*D_];
__device__ float g_k[N_*D_];
__device__ float g_v[N_*D_];
__device__ float g_o[N_*D_];
__device__ float g_xr[N_*D_];    // tf32-rounded x
__device__ float g_wr3[3*D_*D_]; // tf32-rounded Wq|Wk|Wv
__device__ float g_wr[D_*D_];    // tf32-rounded Wo

// ---------------------------------------------------------------------------
// Base-PTX helpers (no tcgen05: harness PTX target is non-'a' sm_103)
// ---------------------------------------------------------------------------
__device__ __forceinline__ void cp16(uint32_t dst, const void* src) {
    asm volatile("cp.async.cg.shared.global [%0], [%1], 16;"
                 :: "r"(dst), "l"(__cvta_generic_to_global(src)));
}
__device__ __forceinline__ void cp_commit() {
    asm volatile("cp.async.commit_group;");
}
template<int N> __device__ __forceinline__ void cp_wait() {
    asm volatile("cp.async.wait_group %0;" :: "n"(N));
}
__device__ __forceinline__ uint32_t f2tf32(float f) {
    uint32_t r;
    asm("cvt.rna.tf32.f32 %0, %1;" : "=r"(r) : "f"(f));
    return r;
}
__device__ __forceinline__ void mma_tf32(float c[4],
                                         const uint32_t a[4],
                                         const uint32_t b[2]) {
    asm volatile(
        "mma.sync.aligned.m16n8k8.row.col.f32.tf32.tf32.f32 "
        "{%0,%1,%2,%3}, {%4,%5,%6,%7}, {%8,%9}, {%0,%1,%2,%3};"
        : "+f"(c[0]), "+f"(c[1]), "+f"(c[2]), "+f"(c[3])
        : "r"(a[0]), "r"(a[1]), "r"(a[2]), "r"(a[3]),
          "r"(b[0]), "r"(b[1]));
}

// ---------------------------------------------------------------------------
// Prepass: fp32 -> tf32-rounded fp32 bits
// ---------------------------------------------------------------------------
__global__ __launch_bounds__(256)
void round_tf32_kernel(const float* __restrict__ in, float* __restrict__ out, int n4) {
    int i = blockIdx.x * blockDim.x + threadIdx.x;
    if (i < n4) {
        float4 v = ((const float4*)in)[i];
        float4 o;
        o.x = __uint_as_float(f2tf32(v.x));
        o.y = __uint_as_float(f2tf32(v.y));
        o.z = __uint_as_float(f2tf32(v.z));
        o.w = __uint_as_float(f2tf32(v.w));
        ((float4*)out)[i] = o;
    }
}

// ---------------------------------------------------------------------------
// tf32 tensor-core GEMM core (pre-rounded inputs, raw-bit fragments).
// ---------------------------------------------------------------------------
#define TM 128
#define TN 128
#define KC 32
#define NCH (D_/KC)
#define STG 2
#define ASTR 36
#define TILE_FLOATS (TM*ASTR)
#define STAGE_FLOATS (2*TILE_FLOATS)
#define GEMM_SMEM (STG*STAGE_FLOATS*4)

__device__ __forceinline__ void load_chunk(const float* __restrict__ A,
                                           const float* __restrict__ W,
                                           int row0, int col0, int c,
                                           float* stage, int tid)
{
    const uint32_t abase = (uint32_t)__cvta_generic_to_shared(stage);
    const uint32_t bbase = (uint32_t)__cvta_generic_to_shared(stage + TILE_FLOATS);
    const char* asrc = (const char*)(A + (size_t)row0 * D_ + c * KC);
    const char* bsrc = (const char*)(W + (size_t)col0 * D_ + c * KC);
#pragma unroll
    for (int i = 0; i < 4; i++) {
        int idx = tid + (i << 8);
        int r = idx >> 3, c16 = idx & 7;
        cp16(abase + (uint32_t)(r * (ASTR*4) + c16 * 16),
             asrc + (size_t)r * (D_*4) + c16 * 16);
    }
#pragma unroll
    for (int i = 0; i < 4; i++) {
        int idx = tid + (i << 8);
        int r = idx >> 3, c16 = idx & 7;
        cp16(bbase + (uint32_t)(r * (ASTR*4) + c16 * 16),
             bsrc + (size_t)r * (D_*4) + c16 * 16);
    }
    cp_commit();
}

template<int ROUND_OUT>
__device__ __forceinline__ void gemm_body(const float* __restrict__ A,
                                          const float* __restrict__ W,
                                          const float* __restrict__ bias,
                                          float* __restrict__ C,
                                          int row0, int col0, float* sm)
{
    const int tid  = threadIdx.x;
    const int lane = tid & 31;
    const int warp = tid >> 5;
    const int wm   = warp & 3;
    const int wn   = warp >> 2;
    const int lr = lane >> 2;
    const int lc = lane & 3;

    float c_f[2][8][4];
#pragma unroll
    for (int mi = 0; mi < 2; mi++)
#pragma unroll
        for (int ni = 0; ni < 8; ni++)
#pragma unroll
            for (int j = 0; j < 4; j++) c_f[mi][ni][j] = 0.f;

    load_chunk(A, W, row0, col0, 0, sm, tid);
    load_chunk(A, W, row0, col0, 1, sm + STAGE_FLOATS, tid);

    for (int kt = 0; kt < NCH; kt++) {
        if (kt >= NCH - 1) cp_wait<0>(); else cp_wait<1>();
        __syncthreads();

        const uint32_t* As = (const uint32_t*)(sm + (kt & 1) * STAGE_FLOATS);
        const uint32_t* Bs = As + TILE_FLOATS;

#pragma unroll
        for (int ks = 0; ks < 4; ks++) {
            const int k0 = ks * 8 + lc;
            uint32_t a_f[2][4];
#pragma unroll
            for (int mi = 0; mi < 2; mi++) {
                int r = wm * 32 + mi * 16 + lr;
                a_f[mi][0] = As[r * ASTR + k0];
                a_f[mi][1] = As[(r + 8) * ASTR + k0];
                a_f[mi][2] = As[r * ASTR + k0 + 4];
                a_f[mi][3] = As[(r + 8) * ASTR + k0 + 4];
            }
            uint32_t b_f[8][2];
#pragma unroll
            for (int ni = 0; ni < 8; ni++) {
                int n = wn * 64 + ni * 8 + lr;
                b_f[ni][0] = Bs[n * ASTR + k0];
                b_f[ni][1] = Bs[n * ASTR + k0 + 4];
            }
#pragma unroll
            for (int mi = 0; mi < 2; mi++)
#pragma unroll
                for (int ni = 0; ni < 8; ni++)
                    mma_tf32(c_f[mi][ni], a_f[mi], b_f[ni]);
        }
        __syncthreads();

        if (kt + STG < NCH)
            load_chunk(A, W, row0, col0, kt + STG,
                       sm + (kt & 1) * STAGE_FLOATS, tid);
    }

#pragma unroll
    for (int ni = 0; ni < 8; ni++) {
        int col = col0 + wn * 64 + ni * 8 + lc * 2;
        float2 bb = *(const float2*)(bias + col);
#pragma unroll
        for (int mi = 0; mi < 2; mi++) {
            int r = row0 + wm * 32 + mi * 16 + lr;
            float2 o0, o1;
            o0.x = c_f[mi][ni][0] + bb.x;
            o0.y = c_f[mi][ni][1] + bb.y;
            o1.x = c_f[mi][ni][2] + bb.x;
            o1.y = c_f[mi][ni][3] + bb.y;
            if (ROUND_OUT) {
                o0.x = __uint_as_float(f2tf32(o0.x));
                o0.y = __uint_as_float(f2tf32(o0.y));
                o1.x = __uint_as_float(f2tf32(o1.x));
                o1.y = __uint_as_float(f2tf32(o1.y));
            }
            *(float2*)(C + (size_t)r * D_ + col)       = o0;
            *(float2*)(C + (size_t)(r + 8) * D_ + col) = o1;
        }
    }
}

// Fused QKV projection: blockIdx.x in [0,24); sel = x>>3 picks Wq/Wk/Wv.
__global__ __launch_bounds__(256, 2)
void gemm_qkv_kernel(const float* __restrict__ A,
                     const float* __restrict__ W3,
                     const float* __restrict__ bq,
                     const float* __restrict__ bk,
                     const float* __restrict__ bv,
                     float* __restrict__ Cq,
                     float* __restrict__ Ck,
                     float* __restrict__ Cv)
{
    extern __shared__ float sm[];
    const int sel  = blockIdx.x >> 3;
    const int col0 = (blockIdx.x & 7) * TN;
    const int row0 = blockIdx.y * TM;
    const float* W = W3 + (size_t)sel * D_ * D_;
    const float* bias = (sel == 0) ? bq : (sel == 1) ? bk : bv;
    float* C = (sel == 0) ? Cq : (sel == 1) ? Ck : Cv;
    gemm_body<1>(A, W, bias, C, row0, col0, sm);
}

// Output projection
__global__ __launch_bounds__(256, 2)
void gemm_o_kernel(const float* __restrict__ A,
                   const float* __restrict__ W,
                   const float* __restrict__ bias,
                   float* __restrict__ C)
{
    extern __shared__ float sm[];
    gemm_body<0>(A, W, bias, C, blockIdx.y * TM, blockIdx.x * TN, sm);
}

// ---------------------------------------------------------------------------
// Flash attention, tf32 mma.sync. CTA = 64 Q rows x one (b,h), 4 warps.
// No Q smem (fragments straight from gmem); smem = 2 KV stages -> 70KB
// -> 3 CTAs/SM.
// ---------------------------------------------------------------------------
#define AK_STR 68
#define AV_STR 72
#define AK_FLOATS (64*AK_STR)
#define AV_FLOATS (64*AV_STR)
#define ASTAGE_FLOATS (AK_FLOATS+AV_FLOATS)
#define ATTN_SMEM (2*ASTAGE_FLOATS*4)   // 71680 bytes

__device__ __forceinline__ void attn_load_kv(const float* __restrict__ kg,
                                             const float* __restrict__ vg,
                                             int kt, float* stage, int tid)
{
    const uint32_t kb = (uint32_t)__cvta_generic_to_shared(stage);
    const uint32_t vb = (uint32_t)__cvta_generic_to_shared(stage + AK_FLOATS);
    const char* ksrc = (const char*)(kg + (size_t)kt * 64 * D_);
    const char* vsrc = (const char*)(vg + (size_t)kt * 64 * D_);
#pragma unroll
    for (int i = 0; i < 8; i++) {           // 64 rows x 64 floats, 128 threads
        int idx = tid + (i << 7);
        int r = idx >> 4, c16 = idx & 15;
        cp16(kb + (uint32_t)(r * (AK_STR*4) + c16 * 16),
             ksrc + (size_t)r * (D_*4) + c16 * 16);
    }
#pragma unroll
    for (int i = 0; i < 8; i++) {
        int idx = tid + (i << 7);
        int r = idx >> 4, c16 = idx & 15;
        cp16(vb + (uint32_t)(r * (AV_STR*4) + c16 * 16),
             vsrc + (size_t)r * (D_*4) + c16 * 16);
    }
    cp_commit();
}

__global__ __launch_bounds__(128, 3)
void attn_mma_kernel(const float* __restrict__ Q,
                     const float* __restrict__ Kg,
                     const float* __restrict__ Vg,
                     float* __restrict__ O)
{
    extern __shared__ float sm[];
    const int tid  = threadIdx.x;
    const int lane = tid & 31;
    const int warp = tid >> 5;   // 0..3
    const int gr   = lane >> 2;
    const int lc   = lane & 3;

    const int q0 = blockIdx.x * 64;
    const int bh = blockIdx.y;
    const int b  = bh >> 4;
    const int h  = bh & 15;

    const float* qg = Q  + ((size_t)(b * S_ + q0)) * D_ + h * HD_;
    const float* kg = Kg + ((size_t)b * S_) * D_ + h * HD_;
    const float* vg = Vg + ((size_t)b * S_) * D_ + h * HD_;

    attn_load_kv(kg, vg, 0, sm, tid);
    attn_load_kv(kg, vg, 1, sm + ASTAGE_FLOATS, tid);

    // Q fragments straight from gmem (pre-rounded tf32; *2^-3 preserves bits)
    uint32_t qf[8][4];
    {
        const float scale = 0.125f;
        const size_t r0 = (size_t)(warp * 16 + gr) * D_;
        const size_t r1 = r0 + 8 * D_;
#pragma unroll
        for (int ks = 0; ks < 8; ks++) {
            const int k0 = ks * 8 + lc;
            qf[ks][0] = __float_as_uint(qg[r0 + k0] * scale);
            qf[ks][1] = __float_as_uint(qg[r1 + k0] * scale);
            qf[ks][2] = __float_as_uint(qg[r0 + k0 + 4] * scale);
            qf[ks][3] = __float_as_uint(qg[r1 + k0 + 4] * scale);
        }
    }

    float co[8][4];
#pragma unroll
    for (int ni = 0; ni < 8; ni++)
#pragma unroll
        for (int j = 0; j < 4; j++) co[ni][j] = 0.f;
    float m0 = -1e30f, m1 = -1e30f, l0 = 0.f, l1 = 0.f;

    const int src  = (lane & ~3) | (lc >> 1);
    const int src2 = src + 2;
    const bool odd = (lc & 1);

    for (int kt = 0; kt < S_/64; kt++) {
        if (kt >= S_/64 - 1) cp_wait<0>(); else cp_wait<1>();
        __syncthreads();

        const uint32_t* Ks = (const uint32_t*)(sm + (kt & 1) * ASTAGE_FLOATS);
        const uint32_t* Vs = Ks + AK_FLOATS;

        // --- S = (scaled Q) @ K^T ---
        float c[8][4];
#pragma unroll
        for (int ni = 0; ni < 8; ni++)
#pragma unroll
            for (int j = 0; j < 4; j++) c[ni][j] = 0.f;

#pragma unroll
        for (int ks = 0; ks < 8; ks++) {
            const int k0 = ks * 8 + lc;
#pragma unroll
            for (int ni = 0; ni < 8; ni++) {
                uint32_t bfr[2];
                const int n = ni * 8 + gr;
                bfr[0] = Ks[n * AK_STR + k0];
                bfr[1] = Ks[n * AK_STR + k0 + 4];
                mma_tf32(c[ni], qf[ks], bfr);
            }
        }

        // --- online softmax ---
        float mt0 = fmaxf(c[0][0], c[0][1]);
        float mt1 = fmaxf(c[0][2], c[0][3]);
#pragma unroll
        for (int ni = 1; ni < 8; ni++) {
            mt0 = fmaxf(mt0, fmaxf(c[ni][0], c[ni][1]));
            mt1 = fmaxf(mt1, fmaxf(c[ni][2], c[ni][3]));
        }
        mt0 = fmaxf(mt0, __shfl_xor_sync(0xffffffffu, mt0, 1));
        mt0 = fmaxf(mt0, __shfl_xor_sync(0xffffffffu, mt0, 2));
        mt1 = fmaxf(mt1, __shfl_xor_sync(0xffffffffu, mt1, 1));
        mt1 = fmaxf(mt1, __shfl_xor_sync(0xffffffffu, mt1, 2));

        const float mn0 = fmaxf(m0, mt0);
        const float mn1 = fmaxf(m1, mt1);
        const float al0 = __expf(m0 - mn0);
        const float al1 = __expf(m1 - mn1);

        float rs0 = 0.f, rs1 = 0.f;
#pragma unroll
        for (int ni = 0; ni < 8; ni++) {
            c[ni][0] = __expf(c[ni][0] - mn0); rs0 += c[ni][0];
            c[ni][1] = __expf(c[ni][1] - mn0); rs0 += c[ni][1];
            c[ni][2] = __expf(c[ni][2] - mn1); rs1 += c[ni][2];
            c[ni][3] = __expf(c[ni][3] - mn1); rs1 += c[ni][3];
        }
        rs0 += __shfl_xor_sync(0xffffffffu, rs0, 1);
        rs0 += __shfl_xor_sync(0xffffffffu, rs0, 2);
        rs1 += __shfl_xor_sync(0xffffffffu, rs1, 1);
        rs1 += __shfl_xor_sync(0xffffffffu, rs1, 2);

        l0 = l0 * al0 + rs0;  m0 = mn0;
        l1 = l1 * al1 + rs1;  m1 = mn1;

#pragma unroll
        for (int ni = 0; ni < 8; ni++) {
            co[ni][0] *= al0; co[ni][1] *= al0;
            co[ni][2] *= al1; co[ni][3] *= al1;
        }

        // --- O += P @ V ---
#pragma unroll
        for (int ks = 0; ks < 8; ks++) {
            float t0 = __shfl_sync(0xffffffffu, c[ks][0], src);
            float t1 = __shfl_sync(0xffffffffu, c[ks][1], src);
            float t2 = __shfl_sync(0xffffffffu, c[ks][2], src);
            float t3 = __shfl_sync(0xffffffffu, c[ks][3], src);
            float u0 = __shfl_sync(0xffffffffu, c[ks][0], src2);
            float u1 = __shfl_sync(0xffffffffu, c[ks][1], src2);
            float u2 = __shfl_sync(0xffffffffu, c[ks][2], src2);
            float u3 = __shfl_sync(0xffffffffu, c[ks][3], src2);
            uint32_t af[4];
            af[0] = f2tf32(odd ? t1 : t0);
            af[1] = f2tf32(odd ? t3 : t2);
            af[2] = f2tf32(odd ? u1 : u0);
            af[3] = f2tf32(odd ? u3 : u2);

            const int kp0 = ks * 8 + lc;
#pragma unroll
            for (int ni = 0; ni < 8; ni++) {
                uint32_t bfr[2];
                const int n = ni * 8 + gr;
                bfr[0] = Vs[kp0 * AV_STR + n];
                bfr[1] = Vs[(kp0 + 4) * AV_STR + n];
                mma_tf32(co[ni], af, bfr);
            }
        }

        __syncthreads();
        if (kt + 2 < S_/64)
            attn_load_kv(kg, vg, kt + 2, sm + (kt & 1) * ASTAGE_FLOATS, tid);
    }

    // --- finalize ---
    const float inv0 = 1.f / l0;
    const float inv1 = 1.f / l1;
    const int n0 = b * S_ + q0 + warp * 16 + gr;
#pragma unroll
    for (int ni = 0; ni < 8; ni++) {
        const int col = h * HD_ + ni * 8 + lc * 2;
        float2 o0, o1;
        o0.x = __uint_as_float(f2tf32(co[ni][0] * inv0));
        o0.y = __uint_as_float(f2tf32(co[ni][1] * inv0));
        o1.x = __uint_as_float(f2tf32(co[ni][2] * inv1));
        o1.y = __uint_as_float(f2tf32(co[ni][3] * inv1));
        *(float2*)(O + (size_t)n0 * D_ + col)       = o0;
        *(float2*)(O + (size_t)(n0 + 8) * D_ + col) = o1;
    }
}

// ---------------------------------------------------------------------------
extern "C" void kernel_launch(void* const* d_in, const int* in_sizes, int n_in,
                              void* d_out, int out_size)
{
    const float* x  = (const float*)d_in[0];
    const float* Wq = (const float*)d_in[1];
    const float* bq = (const float*)d_in[2];
    const float* Wk = (const float*)d_in[3];
    const float* bk = (const float*)d_in[4];
    const float* Wv = (const float*)d_in[5];
    const float* bv = (const float*)d_in[6];
    const float* Wo = (const float*)d_in[7];
    const float* bo = (const float*)d_in[8];
    float* out = (float*)d_out;

    float *qp, *kp, *vp, *op, *xr, *wr3, *wr;
    cudaGetSymbolAddress((void**)&qp, g_q);
    cudaGetSymbolAddress((void**)&kp, g_k);
    cudaGetSymbolAddress((void**)&vp, g_v);
    cudaGetSymbolAddress((void**)&op, g_o);
    cudaGetSymbolAddress((void**)&xr, g_xr);
    cudaGetSymbolAddress((void**)&wr3, g_wr3);
    cudaGetSymbolAddress((void**)&wr, g_wr);

    cudaFuncSetAttribute(gemm_qkv_kernel,
                         cudaFuncAttributeMaxDynamicSharedMemorySize, GEMM_SMEM);
    cudaFuncSetAttribute(gemm_o_kernel,
                         cudaFuncAttributeMaxDynamicSharedMemorySize, GEMM_SMEM);
    cudaFuncSetAttribute(attn_mma_kernel,
                         cudaFuncAttributeMaxDynamicSharedMemorySize, ATTN_SMEM);

    const int n4x = N_ * D_ / 4;
    const int n4w = D_ * D_ / 4;

    round_tf32_kernel<<<n4x / 256, 256>>>(x, xr, n4x);
    round_tf32_kernel<<<n4w / 256, 256>>>(Wq, wr3, n4w);
    round_tf32_kernel<<<n4w / 256, 256>>>(Wk, wr3 + (size_t)D_*D_, n4w);
    round_tf32_kernel<<<n4w / 256, 256>>>(Wv, wr3 + (size_t)2*D_*D_, n4w);

    gemm_qkv_kernel<<<dim3(24, N_ / TM), 256, GEMM_SMEM>>>(
        xr, wr3, bq, bk, bv, qp, kp, vp);

    attn_mma_kernel<<<dim3(S_ / 64, B_ * H_), 128, ATTN_SMEM>>>(qp, kp, vp, op);

    round_tf32_kernel<<<n4w / 256, 256>>>(Wo, wr, n4w);
    gemm_o_kernel<<<dim3(D_ / TN, N_ / TM), 256, GEMM_SMEM>>>(op, wr, bo, out);
}

// round 8
// speedup vs baseline: 6.8056x; 1.7400x over previous
#include <cuda_runtime.h>
#include <cuda_fp16.h>
#include <stdint.h>

#define B_  2
#define S_  2048
#define D_  1024
#define H_  16
#define HD_ 64
#define N_  (B_*S_)   // 4096

// Scratch (allocation-free rule: __device__ globals) — all fp16 now
__device__ __half g_xh[N_*D_];    // x in fp16
__device__ __half g_wh3[3*D_*D_]; // Wq|Wk|Wv fp16
__device__ __half g_wh[D_*D_];    // Wo fp16
__device__ __half g_qh[N_*D_];
__device__ __half g_kh[N_*D_];
__device__ __half g_vh[N_*D_];
__device__ __half g_vt[N_*D_];    // V transposed: [bh][hd][s]
__device__ __half g_oh[N_*D_];    // attention output fp16

// ---------------------------------------------------------------------------
// Base-PTX helpers
// ---------------------------------------------------------------------------
__device__ __forceinline__ void cp16(uint32_t dst, const void* src) {
    asm volatile("cp.async.cg.shared.global [%0], [%1], 16;"
                 :: "r"(dst), "l"(__cvta_generic_to_global(src)));
}
__device__ __forceinline__ void cp_commit() {
    asm volatile("cp.async.commit_group;");
}
template<int N> __device__ __forceinline__ void cp_wait() {
    asm volatile("cp.async.wait_group %0;" :: "n"(N));
}
__device__ __forceinline__ void mma_f16(float c[4],
                                        const uint32_t a[4],
                                        const uint32_t b[2]) {
    asm volatile(
        "mma.sync.aligned.m16n8k16.row.col.f32.f16.f16.f32 "
        "{%0,%1,%2,%3}, {%4,%5,%6,%7}, {%8,%9}, {%0,%1,%2,%3};"
        : "+f"(c[0]), "+f"(c[1]), "+f"(c[2]), "+f"(c[3])
        : "r"(a[0]), "r"(a[1]), "r"(a[2]), "r"(a[3]),
          "r"(b[0]), "r"(b[1]));
}
__device__ __forceinline__ uint32_t packh2(float x, float y) {
    __half2 h = __floats2half2_rn(x, y);
    return *(uint32_t*)&h;
}

// ---------------------------------------------------------------------------
// Prepass: fp32 -> fp16
// ---------------------------------------------------------------------------
__global__ __launch_bounds__(256)
void f32_to_f16_kernel(const float* __restrict__ in, __half* __restrict__ out, int n4) {
    int i = blockIdx.x * blockDim.x + threadIdx.x;
    if (i < n4) {
        float4 v = ((const float4*)in)[i];
        uint2 o;
        o.x = packh2(v.x, v.y);
        o.y = packh2(v.z, v.w);
        ((uint2*)out)[i] = o;
    }
}

// ---------------------------------------------------------------------------
// fp16 tensor-core GEMM: C = A[N_,1024] @ W[1024,1024]^T + bias
// CTA 128x128, 8 warps (4m x 2n), K chunk 32 halves, 2-stage cp.async.
// Smem row stride 40 halves (80B) -> conflict-free fragment LDS.
// ---------------------------------------------------------------------------
#define TM 128
#define TN 128
#define KCH 32                      // halves per chunk
#define NCH (D_/KCH)                // 32
#define RSB 80                      // row stride bytes (40 halves)
#define TILE_BYTES (128*RSB)        // 10240
#define STAGE_BYTES (2*TILE_BYTES)  // 20480
#define GEMM_SMEM (2*STAGE_BYTES)   // 40960

__device__ __forceinline__ void load_chunk_h(const __half* __restrict__ A,
                                             const __half* __restrict__ W,
                                             int row0, int col0, int c,
                                             char* stage, int tid)
{
    const uint32_t abase = (uint32_t)__cvta_generic_to_shared(stage);
    const uint32_t bbase = abase + TILE_BYTES;
    const char* asrc = (const char*)(A + (size_t)row0 * D_ + c * KCH);
    const char* bsrc = (const char*)(W + (size_t)col0 * D_ + c * KCH);
#pragma unroll
    for (int i = 0; i < 2; i++) {          // 128 rows x 64B (4 x cp16)
        int idx = tid + (i << 8);
        int r = idx >> 2, c16 = idx & 3;
        cp16(abase + (uint32_t)(r * RSB + c16 * 16),
             asrc + (size_t)r * (D_*2) + c16 * 16);
    }
#pragma unroll
    for (int i = 0; i < 2; i++) {
        int idx = tid + (i << 8);
        int r = idx >> 2, c16 = idx & 3;
        cp16(bbase + (uint32_t)(r * RSB + c16 * 16),
             bsrc + (size_t)r * (D_*2) + c16 * 16);
    }
    cp_commit();
}

template<int OUT_HALF>
__device__ __forceinline__ void gemm_body_h(const __half* __restrict__ A,
                                            const __half* __restrict__ W,
                                            const float* __restrict__ bias,
                                            void* __restrict__ C,
                                            int row0, int col0, char* sm)
{
    const int tid  = threadIdx.x;
    const int lane = tid & 31;
    const int warp = tid >> 5;
    const int wm   = warp & 3;
    const int wn   = warp >> 2;
    const int gr = lane >> 2;
    const int lc = lane & 3;

    float c_f[2][8][4];
#pragma unroll
    for (int mi = 0; mi < 2; mi++)
#pragma unroll
        for (int ni = 0; ni < 8; ni++)
#pragma unroll
            for (int j = 0; j < 4; j++) c_f[mi][ni][j] = 0.f;

    load_chunk_h(A, W, row0, col0, 0, sm, tid);
    load_chunk_h(A, W, row0, col0, 1, sm + STAGE_BYTES, tid);

    for (int kt = 0; kt < NCH; kt++) {
        if (kt >= NCH - 1) cp_wait<0>(); else cp_wait<1>();
        __syncthreads();

        const uint32_t* As = (const uint32_t*)(sm + (kt & 1) * STAGE_BYTES);
        const uint32_t* Bs = As + TILE_BYTES/4;

#pragma unroll
        for (int ks = 0; ks < 2; ks++) {          // 2 x k16 per 32-half chunk
            const int ko = ks * 8 + lc;           // uint offset within row
            uint32_t a_f[2][4];
#pragma unroll
            for (int mi = 0; mi < 2; mi++) {
                int r = wm * 32 + mi * 16 + gr;
                a_f[mi][0] = As[r * 20 + ko];
                a_f[mi][1] = As[(r + 8) * 20 + ko];
                a_f[mi][2] = As[r * 20 + ko + 4];
                a_f[mi][3] = As[(r + 8) * 20 + ko + 4];
            }
            uint32_t b_f[8][2];
#pragma unroll
            for (int ni = 0; ni < 8; ni++) {
                int n = wn * 64 + ni * 8 + gr;
                b_f[ni][0] = Bs[n * 20 + ko];
                b_f[ni][1] = Bs[n * 20 + ko + 4];
            }
#pragma unroll
            for (int mi = 0; mi < 2; mi++)
#pragma unroll
                for (int ni = 0; ni < 8; ni++)
                    mma_f16(c_f[mi][ni], a_f[mi], b_f[ni]);
        }
        __syncthreads();

        if (kt + 2 < NCH)
            load_chunk_h(A, W, row0, col0, kt + 2,
                         sm + (kt & 1) * STAGE_BYTES, tid);
    }

#pragma unroll
    for (int ni = 0; ni < 8; ni++) {
        int col = col0 + wn * 64 + ni * 8 + lc * 2;
        float2 bb = *(const float2*)(bias + col);
#pragma unroll
        for (int mi = 0; mi < 2; mi++) {
            int r = row0 + wm * 32 + mi * 16 + gr;
            float o00 = c_f[mi][ni][0] + bb.x;
            float o01 = c_f[mi][ni][1] + bb.y;
            float o10 = c_f[mi][ni][2] + bb.x;
            float o11 = c_f[mi][ni][3] + bb.y;
            if (OUT_HALF) {
                __half* Ch = (__half*)C;
                *(uint32_t*)(Ch + (size_t)r * D_ + col)       = packh2(o00, o01);
                *(uint32_t*)(Ch + (size_t)(r + 8) * D_ + col) = packh2(o10, o11);
            } else {
                float* Cf = (float*)C;
                *(float2*)(Cf + (size_t)r * D_ + col)       = make_float2(o00, o01);
                *(float2*)(Cf + (size_t)(r + 8) * D_ + col) = make_float2(o10, o11);
            }
        }
    }
}

// Fused QKV projection
__global__ __launch_bounds__(256, 2)
void gemm_qkv_kernel(const __half* __restrict__ A,
                     const __half* __restrict__ W3,
                     const float* __restrict__ bq,
                     const float* __restrict__ bk,
                     const float* __restrict__ bv,
                     __half* __restrict__ Cq,
                     __half* __restrict__ Ck,
                     __half* __restrict__ Cv)
{
    extern __shared__ char smraw[];
    const int sel  = blockIdx.x >> 3;
    const int col0 = (blockIdx.x & 7) * TN;
    const int row0 = blockIdx.y * TM;
    const __half* W = W3 + (size_t)sel * D_ * D_;
    const float* bias = (sel == 0) ? bq : (sel == 1) ? bk : bv;
    __half* C = (sel == 0) ? Cq : (sel == 1) ? Ck : Cv;
    gemm_body_h<1>(A, W, bias, C, row0, col0, smraw);
}

// Output projection (fp32 out)
__global__ __launch_bounds__(256, 2)
void gemm_o_kernel(const __half* __restrict__ A,
                   const __half* __restrict__ W,
                   const float* __restrict__ bias,
                   float* __restrict__ C)
{
    extern __shared__ char smraw[];
    gemm_body_h<0>(A, W, bias, C, blockIdx.y * TM, blockIdx.x * TN, smraw);
}

// ---------------------------------------------------------------------------
// V transpose: vh [token][D] -> vt [bh][hd=64][s=2048]
// ---------------------------------------------------------------------------
__global__ __launch_bounds__(128)
void transpose_v_kernel(const __half* __restrict__ vh, __half* __restrict__ vt)
{
    __shared__ __half ts[64][72];
    const int tid = threadIdx.x;
    const int s0 = blockIdx.x * 64;
    const int bh = blockIdx.y;
    const int b  = bh >> 4;
    const int h  = bh & 15;

    const __half* src = vh + ((size_t)(b * S_ + s0)) * D_ + h * 64;
#pragma unroll
    for (int i = 0; i < 4; i++) {            // 64 rows x 8 uint4
        int idx = tid + (i << 7);
        int r = idx >> 3, c8 = idx & 7;
        *(uint4*)&ts[r][c8 * 8] = *(const uint4*)(src + (size_t)r * D_ + c8 * 8);
    }
    __syncthreads();

    __half* dst = vt + ((size_t)bh * 64) * S_ + s0;
#pragma unroll
    for (int i = 0; i < 16; i++) {           // 64 hd rows x 32 uint
        int idx = tid + (i << 7);
        int hd = idx >> 5, cu = idx & 31;
        int s = cu * 2;
        __half2 pr = __halves2half2(ts[s][hd], ts[s + 1][hd]);
        *(uint32_t*)(dst + (size_t)hd * S_ + s) = *(uint32_t*)&pr;
    }
}

// ---------------------------------------------------------------------------
// Flash attention, fp16 m16n8k16. CTA = 64 Q rows x one (b,h), 4 warps.
// Smem: 2 stages x (K[64][72] + Vt[64][72]) fp16 = 36864 B -> 4 CTAs/SM.
// ---------------------------------------------------------------------------
#define AK_STRH 72                        // halves
#define ATILE_BYTES (64*AK_STRH*2)        // 9216
#define ASTAGE_BYTES (2*ATILE_BYTES)      // 18432
#define ATTN_SMEM (2*ASTAGE_BYTES)        // 36864

__device__ __forceinline__ void attn_load_kv(const __half* __restrict__ kg,
                                             const __half* __restrict__ vtg,
                                             int kt, char* stage, int tid)
{
    const uint32_t kb = (uint32_t)__cvta_generic_to_shared(stage);
    const uint32_t vb = kb + ATILE_BYTES;
    const char* ksrc = (const char*)(kg + (size_t)kt * 64 * D_);
    const char* vsrc = (const char*)(vtg + (size_t)kt * 64);   // row stride S_
#pragma unroll
    for (int i = 0; i < 4; i++) {          // K: 64 rows x 128B (8 cp16)
        int idx = tid + (i << 7);
        int r = idx >> 3, c16 = idx & 7;
        cp16(kb + (uint32_t)(r * (AK_STRH*2) + c16 * 16),
             ksrc + (size_t)r * (D_*2) + c16 * 16);
    }
#pragma unroll
    for (int i = 0; i < 4; i++) {          // Vt: 64 hd rows x 128B
        int idx = tid + (i << 7);
        int r = idx >> 3, c16 = idx & 7;
        cp16(vb + (uint32_t)(r * (AK_STRH*2) + c16 * 16),
             vsrc + (size_t)r * (S_*2) + c16 * 16);
    }
    cp_commit();
}

__global__ __launch_bounds__(128, 4)
void attn_mma_kernel(const __half* __restrict__ Q,
                     const __half* __restrict__ Kg,
                     const __half* __restrict__ Vt,
                     __half* __restrict__ O)
{
    extern __shared__ char smraw[];
    const int tid  = threadIdx.x;
    const int lane = tid & 31;
    const int warp = tid >> 5;
    const int gr   = lane >> 2;
    const int lc   = lane & 3;

    const int q0 = blockIdx.x * 64;
    const int bh = blockIdx.y;
    const int b  = bh >> 4;
    const int h  = bh & 15;

    const __half* qg  = Q  + ((size_t)(b * S_ + q0)) * D_ + h * HD_;
    const __half* kg  = Kg + ((size_t)b * S_) * D_ + h * HD_;
    const __half* vtg = Vt + ((size_t)bh * 64) * S_;

    attn_load_kv(kg, vtg, 0, smraw, tid);
    attn_load_kv(kg, vtg, 1, smraw + ASTAGE_BYTES, tid);

    // Q fragments straight from gmem, scaled by 0.125 (exact in fp16)
    uint32_t qf[4][4];
    {
        const __half2 sc = __floats2half2_rn(0.125f, 0.125f);
        const __half* q0p = qg + (size_t)(warp * 16 + gr) * D_;
        const __half* q1p = q0p + (size_t)8 * D_;
#pragma unroll
        for (int ks = 0; ks < 4; ks++) {
            const int k0 = ks * 16 + 2 * lc;
            __half2 h0 = __hmul2(*(const __half2*)(q0p + k0), sc);
            __half2 h1 = __hmul2(*(const __half2*)(q1p + k0), sc);
            __half2 h2 = __hmul2(*(const __half2*)(q0p + k0 + 8), sc);
            __half2 h3 = __hmul2(*(const __half2*)(q1p + k0 + 8), sc);
            qf[ks][0] = *(uint32_t*)&h0;
            qf[ks][1] = *(uint32_t*)&h1;
            qf[ks][2] = *(uint32_t*)&h2;
            qf[ks][3] = *(uint32_t*)&h3;
        }
    }

    float co[8][4];
#pragma unroll
    for (int ni = 0; ni < 8; ni++)
#pragma unroll
        for (int j = 0; j < 4; j++) co[ni][j] = 0.f;
    float m0 = -1e30f, m1 = -1e30f, l0 = 0.f, l1 = 0.f;

    for (int kt = 0; kt < S_/64; kt++) {
        if (kt >= S_/64 - 1) cp_wait<0>(); else cp_wait<1>();
        __syncthreads();

        const uint32_t* Ks = (const uint32_t*)(smraw + (kt & 1) * ASTAGE_BYTES);
        const uint32_t* Vs = Ks + ATILE_BYTES/4;

        // --- S = (scaled Q) @ K^T ---
        float c[8][4];
#pragma unroll
        for (int ni = 0; ni < 8; ni++)
#pragma unroll
            for (int j = 0; j < 4; j++) c[ni][j] = 0.f;

#pragma unroll
        for (int ks = 0; ks < 4; ks++) {
            const int ko = ks * 8 + lc;
#pragma unroll
            for (int ni = 0; ni < 8; ni++) {
                uint32_t bfr[2];
                const int n = ni * 8 + gr;
                bfr[0] = Ks[n * 36 + ko];
                bfr[1] = Ks[n * 36 + ko + 4];
                mma_f16(c[ni], qf[ks], bfr);
            }
        }

        // --- online softmax ---
        float mt0 = fmaxf(c[0][0], c[0][1]);
        float mt1 = fmaxf(c[0][2], c[0][3]);
#pragma unroll
        for (int ni = 1; ni < 8; ni++) {
            mt0 = fmaxf(mt0, fmaxf(c[ni][0], c[ni][1]));
            mt1 = fmaxf(mt1, fmaxf(c[ni][2], c[ni][3]));
        }
        mt0 = fmaxf(mt0, __shfl_xor_sync(0xffffffffu, mt0, 1));
        mt0 = fmaxf(mt0, __shfl_xor_sync(0xffffffffu, mt0, 2));
        mt1 = fmaxf(mt1, __shfl_xor_sync(0xffffffffu, mt1, 1));
        mt1 = fmaxf(mt1, __shfl_xor_sync(0xffffffffu, mt1, 2));

        const float mn0 = fmaxf(m0, mt0);
        const float mn1 = fmaxf(m1, mt1);
        const float al0 = __expf(m0 - mn0);
        const float al1 = __expf(m1 - mn1);

        float rs0 = 0.f, rs1 = 0.f;
#pragma unroll
        for (int ni = 0; ni < 8; ni++) {
            c[ni][0] = __expf(c[ni][0] - mn0); rs0 += c[ni][0];
            c[ni][1] = __expf(c[ni][1] - mn0); rs0 += c[ni][1];
            c[ni][2] = __expf(c[ni][2] - mn1); rs1 += c[ni][2];
            c[ni][3] = __expf(c[ni][3] - mn1); rs1 += c[ni][3];
        }
        rs0 += __shfl_xor_sync(0xffffffffu, rs0, 1);
        rs0 += __shfl_xor_sync(0xffffffffu, rs0, 2);
        rs1 += __shfl_xor_sync(0xffffffffu, rs1, 1);
        rs1 += __shfl_xor_sync(0xffffffffu, rs1, 2);

        l0 = l0 * al0 + rs0;  m0 = mn0;
        l1 = l1 * al1 + rs1;  m1 = mn1;

#pragma unroll
        for (int ni = 0; ni < 8; ni++) {
            co[ni][0] *= al0; co[ni][1] *= al0;
            co[ni][2] *= al1; co[ni][3] *= al1;
        }

        // --- O += P @ V : P accum -> fp16 A-fragment is a direct repack ---
#pragma unroll
        for (int ks = 0; ks < 4; ks++) {
            uint32_t af[4];
            af[0] = packh2(c[2*ks][0],   c[2*ks][1]);
            af[1] = packh2(c[2*ks][2],   c[2*ks][3]);
            af[2] = packh2(c[2*ks+1][0], c[2*ks+1][1]);
            af[3] = packh2(c[2*ks+1][2], c[2*ks+1][3]);

            const int ko = ks * 8 + lc;
#pragma unroll
            for (int ni = 0; ni < 8; ni++) {
                uint32_t bfr[2];
                const int n = ni * 8 + gr;
                bfr[0] = Vs[n * 36 + ko];
                bfr[1] = Vs[n * 36 + ko + 4];
                mma_f16(co[ni], af, bfr);
            }
        }

        __syncthreads();
        if (kt + 2 < S_/64)
            attn_load_kv(kg, vtg, kt + 2, smraw + (kt & 1) * ASTAGE_BYTES, tid);
    }

    // --- finalize: O /= l, store fp16 [N][D] ---
    const float inv0 = 1.f / l0;
    const float inv1 = 1.f / l1;
    const int n0 = b * S_ + q0 + warp * 16 + gr;
#pragma unroll
    for (int ni = 0; ni < 8; ni++) {
        const int col = h * HD_ + ni * 8 + lc * 2;
        *(uint32_t*)(O + (size_t)n0 * D_ + col) =
            packh2(co[ni][0] * inv0, co[ni][1] * inv0);
        *(uint32_t*)(O + (size_t)(n0 + 8) * D_ + col) =
            packh2(co[ni][2] * inv1, co[ni][3] * inv1);
    }
}

// ---------------------------------------------------------------------------
extern "C" void kernel_launch(void* const* d_in, const int* in_sizes, int n_in,
                              void* d_out, int out_size)
{
    const float* x  = (const float*)d_in[0];
    const float* Wq = (const float*)d_in[1];
    const float* bq = (const float*)d_in[2];
    const float* Wk = (const float*)d_in[3];
    const float* bk = (const float*)d_in[4];
    const float* Wv = (const float*)d_in[5];
    const float* bv = (const float*)d_in[6];
    const float* Wo = (const float*)d_in[7];
    const float* bo = (const float*)d_in[8];
    float* out = (float*)d_out;

    __half *xh, *wh3, *wh, *qh, *kh, *vh, *vt, *oh;
    cudaGetSymbolAddress((void**)&xh,  g_xh);
    cudaGetSymbolAddress((void**)&wh3, g_wh3);
    cudaGetSymbolAddress((void**)&wh,  g_wh);
    cudaGetSymbolAddress((void**)&qh,  g_qh);
    cudaGetSymbolAddress((void**)&kh,  g_kh);
    cudaGetSymbolAddress((void**)&vh,  g_vh);
    cudaGetSymbolAddress((void**)&vt,  g_vt);
    cudaGetSymbolAddress((void**)&oh,  g_oh);

    cudaFuncSetAttribute(gemm_qkv_kernel,
                         cudaFuncAttributeMaxDynamicSharedMemorySize, GEMM_SMEM);
    cudaFuncSetAttribute(gemm_o_kernel,
                         cudaFuncAttributeMaxDynamicSharedMemorySize, GEMM_SMEM);
    cudaFuncSetAttribute(attn_mma_kernel,
                         cudaFuncAttributeMaxDynamicSharedMemorySize, ATTN_SMEM);

    const int n4x = N_ * D_ / 4;
    const int n4w = D_ * D_ / 4;

    f32_to_f16_kernel<<<n4x / 256, 256>>>(x, xh, n4x);
    f32_to_f16_kernel<<<n4w / 256, 256>>>(Wq, wh3, n4w);
    f32_to_f16_kernel<<<n4w / 256, 256>>>(Wk, wh3 + (size_t)D_*D_, n4w);
    f32_to_f16_kernel<<<n4w / 256, 256>>>(Wv, wh3 + (size_t)2*D_*D_, n4w);
    f32_to_f16_kernel<<<n4w / 256, 256>>>(Wo, wh, n4w);

    gemm_qkv_kernel<<<dim3(24, N_ / TM), 256, GEMM_SMEM>>>(
        xh, wh3, bq, bk, bv, qh, kh, vh);

    transpose_v_kernel<<<dim3(S_ / 64, B_ * H_), 128>>>(vh, vt);

    attn_mma_kernel<<<dim3(S_ / 64, B_ * H_), 128, ATTN_SMEM>>>(qh, kh, vt, oh);

    gemm_o_kernel<<<dim3(D_ / TN, N_ / TM), 256, GEMM_SMEM>>>(oh, wh, bo, out);
}

// round 9
// speedup vs baseline: 7.5442x; 1.1085x over previous
#include <cuda_runtime.h>
#include <cuda_fp16.h>
#include <stdint.h>

#define B_  2
#define S_  2048
#define D_  1024
#define H_  16
#define HD_ 64
#define N_  (B_*S_)   // 4096

// Scratch (allocation-free rule: __device__ globals)
__device__ __half g_xh[N_*D_];    // x fp16
__device__ __half g_wh3[3*D_*D_]; // Wq|Wk|Wv fp16
__device__ __half g_wh[D_*D_];    // Wo fp16
__device__ __half g_qh[N_*D_];
__device__ __half g_kh[N_*D_];
__device__ __half g_vh[N_*D_];
__device__ __half g_oh[N_*D_];    // attention output fp16

// ---------------------------------------------------------------------------
// Base-PTX helpers
// ---------------------------------------------------------------------------
__device__ __forceinline__ void cp16(uint32_t dst, const void* src) {
    asm volatile("cp.async.cg.shared.global [%0], [%1], 16;"
                 :: "r"(dst), "l"(__cvta_generic_to_global(src)));
}
__device__ __forceinline__ void cp_commit() {
    asm volatile("cp.async.commit_group;");
}
template<int N> __device__ __forceinline__ void cp_wait() {
    asm volatile("cp.async.wait_group %0;" :: "n"(N));
}
__device__ __forceinline__ void mma_f16(float c[4],
                                        const uint32_t a[4],
                                        const uint32_t b[2]) {
    asm volatile(
        "mma.sync.aligned.m16n8k16.row.col.f32.f16.f16.f32 "
        "{%0,%1,%2,%3}, {%4,%5,%6,%7}, {%8,%9}, {%0,%1,%2,%3};"
        : "+f"(c[0]), "+f"(c[1]), "+f"(c[2]), "+f"(c[3])
        : "r"(a[0]), "r"(a[1]), "r"(a[2]), "r"(a[3]),
          "r"(b[0]), "r"(b[1]));
}
__device__ __forceinline__ void ldm_x4(uint32_t r[4], uint32_t a) {
    asm volatile("ldmatrix.sync.aligned.m8n8.x4.shared.b16 {%0,%1,%2,%3}, [%4];"
                 : "=r"(r[0]), "=r"(r[1]), "=r"(r[2]), "=r"(r[3]) : "r"(a));
}
__device__ __forceinline__ void ldm_x4_t(uint32_t r[4], uint32_t a) {
    asm volatile("ldmatrix.sync.aligned.m8n8.x4.trans.shared.b16 {%0,%1,%2,%3}, [%4];"
                 : "=r"(r[0]), "=r"(r[1]), "=r"(r[2]), "=r"(r[3]) : "r"(a));
}
__device__ __forceinline__ uint32_t packh2(float x, float y) {
    __half2 h = __floats2half2_rn(x, y);
    return *(uint32_t*)&h;
}

// ---------------------------------------------------------------------------
// Fused prepass: convert x, Wq, Wk, Wv, Wo fp32 -> fp16 in ONE launch
// ---------------------------------------------------------------------------
#define NX4 (N_*D_/4)   // 1048576 float4
#define NW4 (D_*D_/4)   // 262144 float4

__global__ __launch_bounds__(256)
void cvt_all_kernel(const float* __restrict__ x,
                    const float* __restrict__ Wq,
                    const float* __restrict__ Wk,
                    const float* __restrict__ Wv,
                    const float* __restrict__ Wo,
                    __half* __restrict__ xh,
                    __half* __restrict__ wh3,
                    __half* __restrict__ wh)
{
    int i = blockIdx.x * blockDim.x + threadIdx.x;
    const float* src; __half* dst; int off;
    if (i < NX4)              { src = x;  dst = xh;                     off = i; }
    else if (i < NX4 + NW4)   { src = Wq; dst = wh3;                    off = i - NX4; }
    else if (i < NX4 + 2*NW4) { src = Wk; dst = wh3 + (size_t)D_*D_;    off = i - NX4 - NW4; }
    else if (i < NX4 + 3*NW4) { src = Wv; dst = wh3 + (size_t)2*D_*D_;  off = i - NX4 - 2*NW4; }
    else                      { src = Wo; dst = wh;                     off = i - NX4 - 3*NW4; }
    float4 v = ((const float4*)src)[off];
    uint2 o;
    o.x = packh2(v.x, v.y);
    o.y = packh2(v.z, v.w);
    ((uint2*)dst)[off] = o;
}

// ---------------------------------------------------------------------------
// fp16 tensor-core GEMM: C = A[N_,1024] @ W[1024,1024]^T + bias
// CTA 128x128, 8 warps (4m x 2n), K chunk 32 halves, 2-stage cp.async,
// ldmatrix fragment loads. Row stride 40 halves (80B), conflict-free.
// ---------------------------------------------------------------------------
#define TM 128
#define TN 128
#define KCH 32
#define NCH (D_/KCH)                // 32
#define RSB 80                      // row stride bytes
#define TILE_BYTES (128*RSB)        // 10240
#define STAGE_BYTES (2*TILE_BYTES)  // 20480
#define GEMM_SMEM (2*STAGE_BYTES)   // 40960

__device__ __forceinline__ void load_chunk_h(const __half* __restrict__ A,
                                             const __half* __restrict__ W,
                                             int row0, int col0, int c,
                                             char* stage, int tid)
{
    const uint32_t abase = (uint32_t)__cvta_generic_to_shared(stage);
    const uint32_t bbase = abase + TILE_BYTES;
    const char* asrc = (const char*)(A + (size_t)row0 * D_ + c * KCH);
    const char* bsrc = (const char*)(W + (size_t)col0 * D_ + c * KCH);
#pragma unroll
    for (int i = 0; i < 2; i++) {
        int idx = tid + (i << 8);
        int r = idx >> 2, c16 = idx & 3;
        cp16(abase + (uint32_t)(r * RSB + c16 * 16),
             asrc + (size_t)r * (D_*2) + c16 * 16);
    }
#pragma unroll
    for (int i = 0; i < 2; i++) {
        int idx = tid + (i << 8);
        int r = idx >> 2, c16 = idx & 3;
        cp16(bbase + (uint32_t)(r * RSB + c16 * 16),
             bsrc + (size_t)r * (D_*2) + c16 * 16);
    }
    cp_commit();
}

template<int OUT_HALF>
__device__ __forceinline__ void gemm_body_h(const __half* __restrict__ A,
                                            const __half* __restrict__ W,
                                            const float* __restrict__ bias,
                                            void* __restrict__ C,
                                            int row0, int col0, char* sm)
{
    const int tid  = threadIdx.x;
    const int lane = tid & 31;
    const int warp = tid >> 5;
    const int wm   = warp & 3;
    const int wn   = warp >> 2;
    const int gr = lane >> 2;
    const int lc = lane & 3;

    // ldmatrix per-thread offsets
    const uint32_t aoff = (uint32_t)((wm * 32 + (lane & 15)) * RSB + (lane >> 4) * 16);
    const uint32_t boff = (uint32_t)((wn * 64 + (lane & 7) + ((lane >> 4) << 3)) * RSB
                                     + ((lane >> 3) & 1) * 16);
    const uint32_t smb = (uint32_t)__cvta_generic_to_shared(sm);

    float c_f[2][8][4];
#pragma unroll
    for (int mi = 0; mi < 2; mi++)
#pragma unroll
        for (int ni = 0; ni < 8; ni++)
#pragma unroll
            for (int j = 0; j < 4; j++) c_f[mi][ni][j] = 0.f;

    load_chunk_h(A, W, row0, col0, 0, sm, tid);
    load_chunk_h(A, W, row0, col0, 1, sm + STAGE_BYTES, tid);

    for (int kt = 0; kt < NCH; kt++) {
        if (kt >= NCH - 1) cp_wait<0>(); else cp_wait<1>();
        __syncthreads();

        const uint32_t Ab = smb + (kt & 1) * STAGE_BYTES;
        const uint32_t Bb = Ab + TILE_BYTES;

#pragma unroll
        for (int ks = 0; ks < 2; ks++) {
            uint32_t a0[4], a1[4];
            ldm_x4(a0, Ab + aoff + ks * 32);
            ldm_x4(a1, Ab + aoff + 16 * RSB + ks * 32);
#pragma unroll
            for (int p = 0; p < 4; p++) {
                uint32_t br[4];
                ldm_x4(br, Bb + boff + (uint32_t)(p * 16 * RSB + ks * 32));
                mma_f16(c_f[0][2*p],   a0, br);
                mma_f16(c_f[0][2*p+1], a0, br + 2);
                mma_f16(c_f[1][2*p],   a1, br);
                mma_f16(c_f[1][2*p+1], a1, br + 2);
            }
        }
        __syncthreads();

        if (kt + 2 < NCH)
            load_chunk_h(A, W, row0, col0, kt + 2,
                         sm + (kt & 1) * STAGE_BYTES, tid);
    }

#pragma unroll
    for (int ni = 0; ni < 8; ni++) {
        int col = col0 + wn * 64 + ni * 8 + lc * 2;
        float2 bb = *(const float2*)(bias + col);
#pragma unroll
        for (int mi = 0; mi < 2; mi++) {
            int r = row0 + wm * 32 + mi * 16 + gr;
            float o00 = c_f[mi][ni][0] + bb.x;
            float o01 = c_f[mi][ni][1] + bb.y;
            float o10 = c_f[mi][ni][2] + bb.x;
            float o11 = c_f[mi][ni][3] + bb.y;
            if (OUT_HALF) {
                __half* Ch = (__half*)C;
                *(uint32_t*)(Ch + (size_t)r * D_ + col)       = packh2(o00, o01);
                *(uint32_t*)(Ch + (size_t)(r + 8) * D_ + col) = packh2(o10, o11);
            } else {
                float* Cf = (float*)C;
                *(float2*)(Cf + (size_t)r * D_ + col)       = make_float2(o00, o01);
                *(float2*)(Cf + (size_t)(r + 8) * D_ + col) = make_float2(o10, o11);
            }
        }
    }
}

__global__ __launch_bounds__(256, 2)
void gemm_qkv_kernel(const __half* __restrict__ A,
                     const __half* __restrict__ W3,
                     const float* __restrict__ bq,
                     const float* __restrict__ bk,
                     const float* __restrict__ bv,
                     __half* __restrict__ Cq,
                     __half* __restrict__ Ck,
                     __half* __restrict__ Cv)
{
    extern __shared__ char smraw[];
    const int sel  = blockIdx.x >> 3;
    const int col0 = (blockIdx.x & 7) * TN;
    const int row0 = blockIdx.y * TM;
    const __half* W = W3 + (size_t)sel * D_ * D_;
    const float* bias = (sel == 0) ? bq : (sel == 1) ? bk : bv;
    __half* C = (sel == 0) ? Cq : (sel == 1) ? Ck : Cv;
    gemm_body_h<1>(A, W, bias, C, row0, col0, smraw);
}

__global__ __launch_bounds__(256, 2)
void gemm_o_kernel(const __half* __restrict__ A,
                   const __half* __restrict__ W,
                   const float* __restrict__ bias,
                   float* __restrict__ C)
{
    extern __shared__ char smraw[];
    gemm_body_h<0>(A, W, bias, C, blockIdx.y * TM, blockIdx.x * TN, smraw);
}

// ---------------------------------------------------------------------------
// Flash attention, fp16 m16n8k16 + ldmatrix. CTA = 64 Q rows x one (b,h).
// K and V both in natural [token][64] tiles (V via ldmatrix.trans — no
// transpose pass). Smem: 2 stages x 2 tiles x 64 x 144B = 36864 -> 4 CTAs/SM.
// ---------------------------------------------------------------------------
#define AK_STRB 144                       // row stride bytes (72 halves)
#define ATILE_BYTES (64*AK_STRB)          // 9216
#define ASTAGE_BYTES (2*ATILE_BYTES)      // 18432
#define ATTN_SMEM (2*ASTAGE_BYTES)        // 36864

__device__ __forceinline__ void attn_load_kv(const __half* __restrict__ kg,
                                             const __half* __restrict__ vg,
                                             int kt, char* stage, int tid)
{
    const uint32_t kb = (uint32_t)__cvta_generic_to_shared(stage);
    const uint32_t vb = kb + ATILE_BYTES;
    const char* ksrc = (const char*)(kg + (size_t)kt * 64 * D_);
    const char* vsrc = (const char*)(vg + (size_t)kt * 64 * D_);
#pragma unroll
    for (int i = 0; i < 4; i++) {          // 64 rows x 128B (8 cp16)
        int idx = tid + (i << 7);
        int r = idx >> 3, c16 = idx & 7;
        cp16(kb + (uint32_t)(r * AK_STRB + c16 * 16),
             ksrc + (size_t)r * (D_*2) + c16 * 16);
    }
#pragma unroll
    for (int i = 0; i < 4; i++) {
        int idx = tid + (i << 7);
        int r = idx >> 3, c16 = idx & 7;
        cp16(vb + (uint32_t)(r * AK_STRB + c16 * 16),
             vsrc + (size_t)r * (D_*2) + c16 * 16);
    }
    cp_commit();
}

__global__ __launch_bounds__(128, 4)
void attn_mma_kernel(const __half* __restrict__ Q,
                     const __half* __restrict__ Kg,
                     const __half* __restrict__ Vg,
                     __half* __restrict__ O)
{
    extern __shared__ char smraw[];
    const int tid  = threadIdx.x;
    const int lane = tid & 31;
    const int warp = tid >> 5;
    const int gr   = lane >> 2;
    const int lc   = lane & 3;

    const int q0 = blockIdx.x * 64;
    const int bh = blockIdx.y;
    const int b  = bh >> 4;
    const int h  = bh & 15;

    const __half* qg = Q  + ((size_t)(b * S_ + q0)) * D_ + h * HD_;
    const __half* kg = Kg + ((size_t)b * S_) * D_ + h * HD_;
    const __half* vg = Vg + ((size_t)b * S_) * D_ + h * HD_;

    attn_load_kv(kg, vg, 0, smraw, tid);
    attn_load_kv(kg, vg, 1, smraw + ASTAGE_BYTES, tid);

    // ldmatrix per-thread offsets
    const uint32_t koff = (uint32_t)(((lane & 7) + ((lane >> 4) << 3)) * AK_STRB
                                     + ((lane >> 3) & 1) * 16);
    const uint32_t voff = (uint32_t)(((lane & 7) + (((lane >> 3) & 1) << 3)) * AK_STRB
                                     + (lane >> 4) * 16);
    const uint32_t smb = (uint32_t)__cvta_generic_to_shared(smraw);

    // Q fragments straight from gmem, scaled by 0.125 (exact in fp16)
    uint32_t qf[4][4];
    {
        const __half2 sc = __floats2half2_rn(0.125f, 0.125f);
        const __half* q0p = qg + (size_t)(warp * 16 + gr) * D_;
        const __half* q1p = q0p + (size_t)8 * D_;
#pragma unroll
        for (int ks = 0; ks < 4; ks++) {
            const int k0 = ks * 16 + 2 * lc;
            __half2 h0 = __hmul2(*(const __half2*)(q0p + k0), sc);
            __half2 h1 = __hmul2(*(const __half2*)(q1p + k0), sc);
            __half2 h2 = __hmul2(*(const __half2*)(q0p + k0 + 8), sc);
            __half2 h3 = __hmul2(*(const __half2*)(q1p + k0 + 8), sc);
            qf[ks][0] = *(uint32_t*)&h0;
            qf[ks][1] = *(uint32_t*)&h1;
            qf[ks][2] = *(uint32_t*)&h2;
            qf[ks][3] = *(uint32_t*)&h3;
        }
    }

    float co[8][4];
#pragma unroll
    for (int ni = 0; ni < 8; ni++)
#pragma unroll
        for (int j = 0; j < 4; j++) co[ni][j] = 0.f;
    float m0 = -1e30f, m1 = -1e30f, l0 = 0.f, l1 = 0.f;

    for (int kt = 0; kt < S_/64; kt++) {
        if (kt >= S_/64 - 1) cp_wait<0>(); else cp_wait<1>();
        __syncthreads();

        const uint32_t Kb = smb + (kt & 1) * ASTAGE_BYTES;
        const uint32_t Vb = Kb + ATILE_BYTES;

        // --- S = (scaled Q) @ K^T ---
        float c[8][4];
#pragma unroll
        for (int ni = 0; ni < 8; ni++)
#pragma unroll
            for (int j = 0; j < 4; j++) c[ni][j] = 0.f;

#pragma unroll
        for (int ks = 0; ks < 4; ks++) {
#pragma unroll
            for (int p = 0; p < 4; p++) {
                uint32_t br[4];
                ldm_x4(br, Kb + koff + (uint32_t)(p * 16 * AK_STRB + ks * 32));
                mma_f16(c[2*p],   qf[ks], br);
                mma_f16(c[2*p+1], qf[ks], br + 2);
            }
        }

        // --- online softmax ---
        float mt0 = fmaxf(c[0][0], c[0][1]);
        float mt1 = fmaxf(c[0][2], c[0][3]);
#pragma unroll
        for (int ni = 1; ni < 8; ni++) {
            mt0 = fmaxf(mt0, fmaxf(c[ni][0], c[ni][1]));
            mt1 = fmaxf(mt1, fmaxf(c[ni][2], c[ni][3]));
        }
        mt0 = fmaxf(mt0, __shfl_xor_sync(0xffffffffu, mt0, 1));
        mt0 = fmaxf(mt0, __shfl_xor_sync(0xffffffffu, mt0, 2));
        mt1 = fmaxf(mt1, __shfl_xor_sync(0xffffffffu, mt1, 1));
        mt1 = fmaxf(mt1, __shfl_xor_sync(0xffffffffu, mt1, 2));

        const float mn0 = fmaxf(m0, mt0);
        const float mn1 = fmaxf(m1, mt1);
        const float al0 = __expf(m0 - mn0);
        const float al1 = __expf(m1 - mn1);

        float rs0 = 0.f, rs1 = 0.f;
#pragma unroll
        for (int ni = 0; ni < 8; ni++) {
            c[ni][0] = __expf(c[ni][0] - mn0); rs0 += c[ni][0];
            c[ni][1] = __expf(c[ni][1] - mn0); rs0 += c[ni][1];
            c[ni][2] = __expf(c[ni][2] - mn1); rs1 += c[ni][2];
            c[ni][3] = __expf(c[ni][3] - mn1); rs1 += c[ni][3];
        }
        rs0 += __shfl_xor_sync(0xffffffffu, rs0, 1);
        rs0 += __shfl_xor_sync(0xffffffffu, rs0, 2);
        rs1 += __shfl_xor_sync(0xffffffffu, rs1, 1);
        rs1 += __shfl_xor_sync(0xffffffffu, rs1, 2);

        l0 = l0 * al0 + rs0;  m0 = mn0;
        l1 = l1 * al1 + rs1;  m1 = mn1;

#pragma unroll
        for (int ni = 0; ni < 8; ni++) {
            co[ni][0] *= al0; co[ni][1] *= al0;
            co[ni][2] *= al1; co[ni][3] *= al1;
        }

        // --- O += P @ V : P accum -> A-frag direct repack; V via ldmatrix.trans ---
#pragma unroll
        for (int ks = 0; ks < 4; ks++) {
            uint32_t af[4];
            af[0] = packh2(c[2*ks][0],   c[2*ks][1]);
            af[1] = packh2(c[2*ks][2],   c[2*ks][3]);
            af[2] = packh2(c[2*ks+1][0], c[2*ks+1][1]);
            af[3] = packh2(c[2*ks+1][2], c[2*ks+1][3]);
#pragma unroll
            for (int p = 0; p < 4; p++) {
                uint32_t br[4];
                ldm_x4_t(br, Vb + voff + (uint32_t)(ks * 16 * AK_STRB + p * 32));
                mma_f16(co[2*p],   af, br);
                mma_f16(co[2*p+1], af, br + 2);
            }
        }

        __syncthreads();
        if (kt + 2 < S_/64)
            attn_load_kv(kg, vg, kt + 2, smraw + (kt & 1) * ASTAGE_BYTES, tid);
    }

    // --- finalize: O /= l, store fp16 [N][D] ---
    const float inv0 = 1.f / l0;
    const float inv1 = 1.f / l1;
    const int n0 = b * S_ + q0 + warp * 16 + gr;
#pragma unroll
    for (int ni = 0; ni < 8; ni++) {
        const int col = h * HD_ + ni * 8 + lc * 2;
        *(uint32_t*)(O + (size_t)n0 * D_ + col) =
            packh2(co[ni][0] * inv0, co[ni][1] * inv0);
        *(uint32_t*)(O + (size_t)(n0 + 8) * D_ + col) =
            packh2(co[ni][2] * inv1, co[ni][3] * inv1);
    }
}

// ---------------------------------------------------------------------------
extern "C" void kernel_launch(void* const* d_in, const int* in_sizes, int n_in,
                              void* d_out, int out_size)
{
    const float* x  = (const float*)d_in[0];
    const float* Wq = (const float*)d_in[1];
    const float* bq = (const float*)d_in[2];
    const float* Wk = (const float*)d_in[3];
    const float* bk = (const float*)d_in[4];
    const float* Wv = (const float*)d_in[5];
    const float* bv = (const float*)d_in[6];
    const float* Wo = (const float*)d_in[7];
    const float* bo = (const float*)d_in[8];
    float* out = (float*)d_out;

    __half *xh, *wh3, *wh, *qh, *kh, *vh, *oh;
    cudaGetSymbolAddress((void**)&xh,  g_xh);
    cudaGetSymbolAddress((void**)&wh3, g_wh3);
    cudaGetSymbolAddress((void**)&wh,  g_wh);
    cudaGetSymbolAddress((void**)&qh,  g_qh);
    cudaGetSymbolAddress((void**)&kh,  g_kh);
    cudaGetSymbolAddress((void**)&vh,  g_vh);
    cudaGetSymbolAddress((void**)&oh,  g_oh);

    cudaFuncSetAttribute(gemm_qkv_kernel,
                         cudaFuncAttributeMaxDynamicSharedMemorySize, GEMM_SMEM);
    cudaFuncSetAttribute(gemm_o_kernel,
                         cudaFuncAttributeMaxDynamicSharedMemorySize, GEMM_SMEM);
    cudaFuncSetAttribute(attn_mma_kernel,
                         cudaFuncAttributeMaxDynamicSharedMemorySize, ATTN_SMEM);

    const int ntot4 = NX4 + 4 * NW4;   // 2097152
    cvt_all_kernel<<<ntot4 / 256, 256>>>(x, Wq, Wk, Wv, Wo, xh, wh3, wh);

    gemm_qkv_kernel<<<dim3(24, N_ / TM), 256, GEMM_SMEM>>>(
        xh, wh3, bq, bk, bv, qh, kh, vh);

    attn_mma_kernel<<<dim3(S_ / 64, B_ * H_), 128, ATTN_SMEM>>>(qh, kh, vh, oh);

    gemm_o_kernel<<<dim3(D_ / TN, N_ / TM), 256, GEMM_SMEM>>>(oh, wh, bo, out);
}

// round 10
// speedup vs baseline: 7.9270x; 1.0507x over previous
#include <cuda_runtime.h>
#include <cuda_fp16.h>
#include <stdint.h>

#define B_  2
#define S_  2048
#define D_  1024
#define H_  16
#define HD_ 64
#define N_  (B_*S_)   // 4096

// Scratch (allocation-free rule: __device__ globals)
__device__ __half g_xh[N_*D_];    // x fp16
__device__ __half g_wh3[3*D_*D_]; // Wq|Wk|Wv fp16
__device__ __half g_wh[D_*D_];    // Wo fp16
__device__ __half g_qh[N_*D_];
__device__ __half g_kh[N_*D_];
__device__ __half g_vh[N_*D_];
__device__ __half g_oh[N_*D_];    // attention output fp16

// ---------------------------------------------------------------------------
// Base-PTX helpers
// ---------------------------------------------------------------------------
__device__ __forceinline__ void cp16(uint32_t dst, const void* src) {
    asm volatile("cp.async.cg.shared.global [%0], [%1], 16;"
                 :: "r"(dst), "l"(__cvta_generic_to_global(src)));
}
__device__ __forceinline__ void cp_commit() {
    asm volatile("cp.async.commit_group;");
}
template<int N> __device__ __forceinline__ void cp_wait() {
    asm volatile("cp.async.wait_group %0;" :: "n"(N));
}
__device__ __forceinline__ void mma_f16(float c[4],
                                        const uint32_t a[4],
                                        const uint32_t b[2]) {
    asm volatile(
        "mma.sync.aligned.m16n8k16.row.col.f32.f16.f16.f32 "
        "{%0,%1,%2,%3}, {%4,%5,%6,%7}, {%8,%9}, {%0,%1,%2,%3};"
        : "+f"(c[0]), "+f"(c[1]), "+f"(c[2]), "+f"(c[3])
        : "r"(a[0]), "r"(a[1]), "r"(a[2]), "r"(a[3]),
          "r"(b[0]), "r"(b[1]));
}
__device__ __forceinline__ void ldm_x4(uint32_t r[4], uint32_t a) {
    asm volatile("ldmatrix.sync.aligned.m8n8.x4.shared.b16 {%0,%1,%2,%3}, [%4];"
                 : "=r"(r[0]), "=r"(r[1]), "=r"(r[2]), "=r"(r[3]) : "r"(a));
}
__device__ __forceinline__ void ldm_x4_t(uint32_t r[4], uint32_t a) {
    asm volatile("ldmatrix.sync.aligned.m8n8.x4.trans.shared.b16 {%0,%1,%2,%3}, [%4];"
                 : "=r"(r[0]), "=r"(r[1]), "=r"(r[2]), "=r"(r[3]) : "r"(a));
}
__device__ __forceinline__ uint32_t packh2(float x, float y) {
    __half2 h = __floats2half2_rn(x, y);
    return *(uint32_t*)&h;
}

// ---------------------------------------------------------------------------
// Fused prepass: convert x, Wq, Wk, Wv, Wo fp32 -> fp16 in ONE launch
// ---------------------------------------------------------------------------
#define NX4 (N_*D_/4)   // 1048576
#define NW4 (D_*D_/4)   // 262144

__global__ __launch_bounds__(256)
void cvt_all_kernel(const float* __restrict__ x,
                    const float* __restrict__ Wq,
                    const float* __restrict__ Wk,
                    const float* __restrict__ Wv,
                    const float* __restrict__ Wo,
                    __half* __restrict__ xh,
                    __half* __restrict__ wh3,
                    __half* __restrict__ wh)
{
    int i = blockIdx.x * blockDim.x + threadIdx.x;
    const float* src; __half* dst; int off;
    if (i < NX4)              { src = x;  dst = xh;                     off = i; }
    else if (i < NX4 + NW4)   { src = Wq; dst = wh3;                    off = i - NX4; }
    else if (i < NX4 + 2*NW4) { src = Wk; dst = wh3 + (size_t)D_*D_;    off = i - NX4 - NW4; }
    else if (i < NX4 + 3*NW4) { src = Wv; dst = wh3 + (size_t)2*D_*D_;  off = i - NX4 - 2*NW4; }
    else                      { src = Wo; dst = wh;                     off = i - NX4 - 3*NW4; }
    float4 v = ((const float4*)src)[off];
    uint2 o;
    o.x = packh2(v.x, v.y);
    o.y = packh2(v.z, v.w);
    ((uint2*)dst)[off] = o;
}

// ---------------------------------------------------------------------------
// fp16 tensor-core GEMM, 4-stage cp.async ring, ONE barrier per k-chunk.
// CTA 128x128, 8 warps, K chunk 32 halves, ldmatrix fragments, stride 80B.
// ---------------------------------------------------------------------------
#define TM 128
#define TN 128
#define KCH 32
#define NCH (D_/KCH)                // 32
#define GSTG 4
#define RSB 80
#define TILE_BYTES (128*RSB)        // 10240
#define STAGE_BYTES (2*TILE_BYTES)  // 20480
#define GEMM_SMEM (GSTG*STAGE_BYTES) // 81920

// Loads chunk c (guarded); ALWAYS commits a group (possibly empty).
__device__ __forceinline__ void load_chunk_h(const __half* __restrict__ A,
                                             const __half* __restrict__ W,
                                             int row0, int col0, int c,
                                             char* stage, int tid)
{
    if (c < NCH) {
        const uint32_t abase = (uint32_t)__cvta_generic_to_shared(stage);
        const uint32_t bbase = abase + TILE_BYTES;
        const char* asrc = (const char*)(A + (size_t)row0 * D_ + c * KCH);
        const char* bsrc = (const char*)(W + (size_t)col0 * D_ + c * KCH);
#pragma unroll
        for (int i = 0; i < 2; i++) {
            int idx = tid + (i << 8);
            int r = idx >> 2, c16 = idx & 3;
            cp16(abase + (uint32_t)(r * RSB + c16 * 16),
                 asrc + (size_t)r * (D_*2) + c16 * 16);
        }
#pragma unroll
        for (int i = 0; i < 2; i++) {
            int idx = tid + (i << 8);
            int r = idx >> 2, c16 = idx & 3;
            cp16(bbase + (uint32_t)(r * RSB + c16 * 16),
                 bsrc + (size_t)r * (D_*2) + c16 * 16);
        }
    }
    cp_commit();
}

template<int OUT_HALF>
__device__ __forceinline__ void gemm_body_h(const __half* __restrict__ A,
                                            const __half* __restrict__ W,
                                            const float* __restrict__ bias,
                                            void* __restrict__ C,
                                            int row0, int col0, char* sm)
{
    const int tid  = threadIdx.x;
    const int lane = tid & 31;
    const int warp = tid >> 5;
    const int wm   = warp & 3;
    const int wn   = warp >> 2;
    const int gr = lane >> 2;
    const int lc = lane & 3;

    const uint32_t aoff = (uint32_t)((wm * 32 + (lane & 15)) * RSB + (lane >> 4) * 16);
    const uint32_t boff = (uint32_t)((wn * 64 + (lane & 7) + ((lane >> 4) << 3)) * RSB
                                     + ((lane >> 3) & 1) * 16);
    const uint32_t smb = (uint32_t)__cvta_generic_to_shared(sm);

    float c_f[2][8][4];
#pragma unroll
    for (int mi = 0; mi < 2; mi++)
#pragma unroll
        for (int ni = 0; ni < 8; ni++)
#pragma unroll
            for (int j = 0; j < 4; j++) c_f[mi][ni][j] = 0.f;

    // Prologue: chunks 0..2 into stages 0..2
#pragma unroll
    for (int s = 0; s < GSTG - 1; s++)
        load_chunk_h(A, W, row0, col0, s, sm + s * STAGE_BYTES, tid);

    for (int kt = 0; kt < NCH; kt++) {
        cp_wait<GSTG - 2>();          // chunk kt complete (uniform: empty tail groups)
        __syncthreads();              // all warps done with stage (kt-1)%GSTG

        // Issue next load into the stage freed last iteration
        load_chunk_h(A, W, row0, col0, kt + GSTG - 1,
                     sm + ((kt + GSTG - 1) & (GSTG - 1)) * STAGE_BYTES, tid);

        const uint32_t Ab = smb + (kt & (GSTG - 1)) * STAGE_BYTES;
        const uint32_t Bb = Ab + TILE_BYTES;

#pragma unroll
        for (int ks = 0; ks < 2; ks++) {
            uint32_t a0[4], a1[4];
            ldm_x4(a0, Ab + aoff + ks * 32);
            ldm_x4(a1, Ab + aoff + 16 * RSB + ks * 32);
#pragma unroll
            for (int p = 0; p < 4; p++) {
                uint32_t br[4];
                ldm_x4(br, Bb + boff + (uint32_t)(p * 16 * RSB + ks * 32));
                mma_f16(c_f[0][2*p],   a0, br);
                mma_f16(c_f[0][2*p+1], a0, br + 2);
                mma_f16(c_f[1][2*p],   a1, br);
                mma_f16(c_f[1][2*p+1], a1, br + 2);
            }
        }
    }

#pragma unroll
    for (int ni = 0; ni < 8; ni++) {
        int col = col0 + wn * 64 + ni * 8 + lc * 2;
        float2 bb = *(const float2*)(bias + col);
#pragma unroll
        for (int mi = 0; mi < 2; mi++) {
            int r = row0 + wm * 32 + mi * 16 + gr;
            float o00 = c_f[mi][ni][0] + bb.x;
            float o01 = c_f[mi][ni][1] + bb.y;
            float o10 = c_f[mi][ni][2] + bb.x;
            float o11 = c_f[mi][ni][3] + bb.y;
            if (OUT_HALF) {
                __half* Ch = (__half*)C;
                *(uint32_t*)(Ch + (size_t)r * D_ + col)       = packh2(o00, o01);
                *(uint32_t*)(Ch + (size_t)(r + 8) * D_ + col) = packh2(o10, o11);
            } else {
                float* Cf = (float*)C;
                *(float2*)(Cf + (size_t)r * D_ + col)       = make_float2(o00, o01);
                *(float2*)(Cf + (size_t)(r + 8) * D_ + col) = make_float2(o10, o11);
            }
        }
    }
}

__global__ __launch_bounds__(256, 2)
void gemm_qkv_kernel(const __half* __restrict__ A,
                     const __half* __restrict__ W3,
                     const float* __restrict__ bq,
                     const float* __restrict__ bk,
                     const float* __restrict__ bv,
                     __half* __restrict__ Cq,
                     __half* __restrict__ Ck,
                     __half* __restrict__ Cv)
{
    extern __shared__ char smraw[];
    const int sel  = blockIdx.x >> 3;
    const int col0 = (blockIdx.x & 7) * TN;
    const int row0 = blockIdx.y * TM;
    const __half* W = W3 + (size_t)sel * D_ * D_;
    const float* bias = (sel == 0) ? bq : (sel == 1) ? bk : bv;
    __half* C = (sel == 0) ? Cq : (sel == 1) ? Ck : Cv;
    gemm_body_h<1>(A, W, bias, C, row0, col0, smraw);
}

__global__ __launch_bounds__(256, 2)
void gemm_o_kernel(const __half* __restrict__ A,
                   const __half* __restrict__ W,
                   const float* __restrict__ bias,
                   float* __restrict__ C)
{
    extern __shared__ char smraw[];
    gemm_body_h<0>(A, W, bias, C, blockIdx.y * TM, blockIdx.x * TN, smraw);
}

// ---------------------------------------------------------------------------
// Flash attention, fp16 + ldmatrix, 3-stage KV ring, ONE barrier per tile.
// CTA = 64 Q rows x one (b,h), 4 warps. Smem 3 x 18432 = 55296 -> 4 CTAs/SM.
// ---------------------------------------------------------------------------
#define ASTG 3
#define AK_STRB 144
#define ATILE_BYTES (64*AK_STRB)          // 9216
#define ASTAGE_BYTES (2*ATILE_BYTES)      // 18432
#define ATTN_SMEM (ASTG*ASTAGE_BYTES)     // 55296
#define NKT (S_/64)                       // 32

__device__ __forceinline__ void attn_load_kv(const __half* __restrict__ kg,
                                             const __half* __restrict__ vg,
                                             int kt, char* stage, int tid)
{
    if (kt < NKT) {
        const uint32_t kb = (uint32_t)__cvta_generic_to_shared(stage);
        const uint32_t vb = kb + ATILE_BYTES;
        const char* ksrc = (const char*)(kg + (size_t)kt * 64 * D_);
        const char* vsrc = (const char*)(vg + (size_t)kt * 64 * D_);
#pragma unroll
        for (int i = 0; i < 4; i++) {
            int idx = tid + (i << 7);
            int r = idx >> 3, c16 = idx & 7;
            cp16(kb + (uint32_t)(r * AK_STRB + c16 * 16),
                 ksrc + (size_t)r * (D_*2) + c16 * 16);
        }
#pragma unroll
        for (int i = 0; i < 4; i++) {
            int idx = tid + (i << 7);
            int r = idx >> 3, c16 = idx & 7;
            cp16(vb + (uint32_t)(r * AK_STRB + c16 * 16),
                 vsrc + (size_t)r * (D_*2) + c16 * 16);
        }
    }
    cp_commit();
}

__global__ __launch_bounds__(128, 4)
void attn_mma_kernel(const __half* __restrict__ Q,
                     const __half* __restrict__ Kg,
                     const __half* __restrict__ Vg,
                     __half* __restrict__ O)
{
    extern __shared__ char smraw[];
    const int tid  = threadIdx.x;
    const int lane = tid & 31;
    const int warp = tid >> 5;
    const int gr   = lane >> 2;
    const int lc   = lane & 3;

    const int q0 = blockIdx.x * 64;
    const int bh = blockIdx.y;
    const int b  = bh >> 4;
    const int h  = bh & 15;

    const __half* qg = Q  + ((size_t)(b * S_ + q0)) * D_ + h * HD_;
    const __half* kg = Kg + ((size_t)b * S_) * D_ + h * HD_;
    const __half* vg = Vg + ((size_t)b * S_) * D_ + h * HD_;

    // Prologue: KV tiles 0,1
    attn_load_kv(kg, vg, 0, smraw, tid);
    attn_load_kv(kg, vg, 1, smraw + ASTAGE_BYTES, tid);

    const uint32_t koff = (uint32_t)(((lane & 7) + ((lane >> 4) << 3)) * AK_STRB
                                     + ((lane >> 3) & 1) * 16);
    const uint32_t voff = (uint32_t)(((lane & 7) + (((lane >> 3) & 1) << 3)) * AK_STRB
                                     + (lane >> 4) * 16);
    const uint32_t smb = (uint32_t)__cvta_generic_to_shared(smraw);

    // Q fragments straight from gmem (scale 2^-3 exact in fp16)
    uint32_t qf[4][4];
    {
        const __half2 sc = __floats2half2_rn(0.125f, 0.125f);
        const __half* q0p = qg + (size_t)(warp * 16 + gr) * D_;
        const __half* q1p = q0p + (size_t)8 * D_;
#pragma unroll
        for (int ks = 0; ks < 4; ks++) {
            const int k0 = ks * 16 + 2 * lc;
            __half2 h0 = __hmul2(*(const __half2*)(q0p + k0), sc);
            __half2 h1 = __hmul2(*(const __half2*)(q1p + k0), sc);
            __half2 h2 = __hmul2(*(const __half2*)(q0p + k0 + 8), sc);
            __half2 h3 = __hmul2(*(const __half2*)(q1p + k0 + 8), sc);
            qf[ks][0] = *(uint32_t*)&h0;
            qf[ks][1] = *(uint32_t*)&h1;
            qf[ks][2] = *(uint32_t*)&h2;
            qf[ks][3] = *(uint32_t*)&h3;
        }
    }

    float co[8][4];
#pragma unroll
    for (int ni = 0; ni < 8; ni++)
#pragma unroll
        for (int j = 0; j < 4; j++) co[ni][j] = 0.f;
    float m0 = -1e30f, m1 = -1e30f, l0 = 0.f, l1 = 0.f;

    int stg = 0;        // stage of tile kt
    for (int kt = 0; kt < NKT; kt++) {
        cp_wait<1>();                 // tile kt complete
        __syncthreads();              // all warps done with stage of tile kt-1

        // Issue tile kt+2 into the stage freed last iteration
        int wst = stg + 2; if (wst >= ASTG) wst -= ASTG;
        attn_load_kv(kg, vg, kt + 2, smraw + wst * ASTAGE_BYTES, tid);

        const uint32_t Kb = smb + stg * ASTAGE_BYTES;
        const uint32_t Vb = Kb + ATILE_BYTES;

        // --- S = (scaled Q) @ K^T ---
        float c[8][4];
#pragma unroll
        for (int ni = 0; ni < 8; ni++)
#pragma unroll
            for (int j = 0; j < 4; j++) c[ni][j] = 0.f;

#pragma unroll
        for (int ks = 0; ks < 4; ks++) {
#pragma unroll
            for (int p = 0; p < 4; p++) {
                uint32_t br[4];
                ldm_x4(br, Kb + koff + (uint32_t)(p * 16 * AK_STRB + ks * 32));
                mma_f16(c[2*p],   qf[ks], br);
                mma_f16(c[2*p+1], qf[ks], br + 2);
            }
        }

        // --- online softmax ---
        float mt0 = fmaxf(c[0][0], c[0][1]);
        float mt1 = fmaxf(c[0][2], c[0][3]);
#pragma unroll
        for (int ni = 1; ni < 8; ni++) {
            mt0 = fmaxf(mt0, fmaxf(c[ni][0], c[ni][1]));
            mt1 = fmaxf(mt1, fmaxf(c[ni][2], c[ni][3]));
        }
        mt0 = fmaxf(mt0, __shfl_xor_sync(0xffffffffu, mt0, 1));
        mt0 = fmaxf(mt0, __shfl_xor_sync(0xffffffffu, mt0, 2));
        mt1 = fmaxf(mt1, __shfl_xor_sync(0xffffffffu, mt1, 1));
        mt1 = fmaxf(mt1, __shfl_xor_sync(0xffffffffu, mt1, 2));

        const float mn0 = fmaxf(m0, mt0);
        const float mn1 = fmaxf(m1, mt1);
        const float al0 = __expf(m0 - mn0);
        const float al1 = __expf(m1 - mn1);

        float rs0 = 0.f, rs1 = 0.f;
#pragma unroll
        for (int ni = 0; ni < 8; ni++) {
            c[ni][0] = __expf(c[ni][0] - mn0); rs0 += c[ni][0];
            c[ni][1] = __expf(c[ni][1] - mn0); rs0 += c[ni][1];
            c[ni][2] = __expf(c[ni][2] - mn1); rs1 += c[ni][2];
            c[ni][3] = __expf(c[ni][3] - mn1); rs1 += c[ni][3];
        }
        rs0 += __shfl_xor_sync(0xffffffffu, rs0, 1);
        rs0 += __shfl_xor_sync(0xffffffffu, rs0, 2);
        rs1 += __shfl_xor_sync(0xffffffffu, rs1, 1);
        rs1 += __shfl_xor_sync(0xffffffffu, rs1, 2);

        l0 = l0 * al0 + rs0;  m0 = mn0;
        l1 = l1 * al1 + rs1;  m1 = mn1;

#pragma unroll
        for (int ni = 0; ni < 8; ni++) {
            co[ni][0] *= al0; co[ni][1] *= al0;
            co[ni][2] *= al1; co[ni][3] *= al1;
        }

        // --- O += P @ V (V via ldmatrix.trans) ---
#pragma unroll
        for (int ks = 0; ks < 4; ks++) {
            uint32_t af[4];
            af[0] = packh2(c[2*ks][0],   c[2*ks][1]);
            af[1] = packh2(c[2*ks][2],   c[2*ks][3]);
            af[2] = packh2(c[2*ks+1][0], c[2*ks+1][1]);
            af[3] = packh2(c[2*ks+1][2], c[2*ks+1][3]);
#pragma unroll
            for (int p = 0; p < 4; p++) {
                uint32_t br[4];
                ldm_x4_t(br, Vb + voff + (uint32_t)(ks * 16 * AK_STRB + p * 32));
                mma_f16(co[2*p],   af, br);
                mma_f16(co[2*p+1], af, br + 2);
            }
        }

        if (++stg == ASTG) stg = 0;
    }

    // --- finalize ---
    const float inv0 = 1.f / l0;
    const float inv1 = 1.f / l1;
    const int n0 = b * S_ + q0 + warp * 16 + gr;
#pragma unroll
    for (int ni = 0; ni < 8; ni++) {
        const int col = h * HD_ + ni * 8 + lc * 2;
        *(uint32_t*)(O + (size_t)n0 * D_ + col) =
            packh2(co[ni][0] * inv0, co[ni][1] * inv0);
        *(uint32_t*)(O + (size_t)(n0 + 8) * D_ + col) =
            packh2(co[ni][2] * inv1, co[ni][3] * inv1);
    }
}

// ---------------------------------------------------------------------------
extern "C" void kernel_launch(void* const* d_in, const int* in_sizes, int n_in,
                              void* d_out, int out_size)
{
    const float* x  = (const float*)d_in[0];
    const float* Wq = (const float*)d_in[1];
    const float* bq = (const float*)d_in[2];
    const float* Wk = (const float*)d_in[3];
    const float* bk = (const float*)d_in[4];
    const float* Wv = (const float*)d_in[5];
    const float* bv = (const float*)d_in[6];
    const float* Wo = (const float*)d_in[7];
    const float* bo = (const float*)d_in[8];
    float* out = (float*)d_out;

    __half *xh, *wh3, *wh, *qh, *kh, *vh, *oh;
    cudaGetSymbolAddress((void**)&xh,  g_xh);
    cudaGetSymbolAddress((void**)&wh3, g_wh3);
    cudaGetSymbolAddress((void**)&wh,  g_wh);
    cudaGetSymbolAddress((void**)&qh,  g_qh);
    cudaGetSymbolAddress((void**)&kh,  g_kh);
    cudaGetSymbolAddress((void**)&vh,  g_vh);
    cudaGetSymbolAddress((void**)&oh,  g_oh);

    cudaFuncSetAttribute(gemm_qkv_kernel,
                         cudaFuncAttributeMaxDynamicSharedMemorySize, GEMM_SMEM);
    cudaFuncSetAttribute(gemm_o_kernel,
                         cudaFuncAttributeMaxDynamicSharedMemorySize, GEMM_SMEM);
    cudaFuncSetAttribute(attn_mma_kernel,
                         cudaFuncAttributeMaxDynamicSharedMemorySize, ATTN_SMEM);

    const int ntot4 = NX4 + 4 * NW4;
    cvt_all_kernel<<<ntot4 / 256, 256>>>(x, Wq, Wk, Wv, Wo, xh, wh3, wh);

    gemm_qkv_kernel<<<dim3(24, N_ / TM), 256, GEMM_SMEM>>>(
        xh, wh3, bq, bk, bv, qh, kh, vh);

    attn_mma_kernel<<<dim3(S_ / 64, B_ * H_), 128, ATTN_SMEM>>>(qh, kh, vh, oh);

    gemm_o_kernel<<<dim3(D_ / TN, N_ / TM), 256, GEMM_SMEM>>>(oh, wh, bo, out);
}

// round 11
// speedup vs baseline: 8.5631x; 1.0802x over previous
#include <cuda_runtime.h>
#include <cuda_fp16.h>
#include <stdint.h>

#define B_  2
#define S_  2048
#define D_  1024
#define H_  16
#define HD_ 64
#define N_  (B_*S_)   // 4096

// Scratch (allocation-free rule: __device__ globals)
__device__ __half g_xh[N_*D_];
__device__ __half g_wh3[3*D_*D_];
__device__ __half g_wh[D_*D_];
__device__ __half g_qh[N_*D_];
__device__ __half g_kh[N_*D_];
__device__ __half g_vh[N_*D_];
__device__ __half g_oh[N_*D_];

// ---------------------------------------------------------------------------
// Base-PTX helpers
// ---------------------------------------------------------------------------
__device__ __forceinline__ void cp16(uint32_t dst, const void* src) {
    asm volatile("cp.async.cg.shared.global [%0], [%1], 16;"
                 :: "r"(dst), "l"(__cvta_generic_to_global(src)));
}
__device__ __forceinline__ void cp_commit() {
    asm volatile("cp.async.commit_group;");
}
template<int N> __device__ __forceinline__ void cp_wait() {
    asm volatile("cp.async.wait_group %0;" :: "n"(N));
}
__device__ __forceinline__ void mma_f16(float c[4],
                                        const uint32_t a[4],
                                        const uint32_t b[2]) {
    asm volatile(
        "mma.sync.aligned.m16n8k16.row.col.f32.f16.f16.f32 "
        "{%0,%1,%2,%3}, {%4,%5,%6,%7}, {%8,%9}, {%0,%1,%2,%3};"
        : "+f"(c[0]), "+f"(c[1]), "+f"(c[2]), "+f"(c[3])
        : "r"(a[0]), "r"(a[1]), "r"(a[2]), "r"(a[3]),
          "r"(b[0]), "r"(b[1]));
}
__device__ __forceinline__ void ldm_x4(uint32_t r[4], uint32_t a) {
    asm volatile("ldmatrix.sync.aligned.m8n8.x4.shared.b16 {%0,%1,%2,%3}, [%4];"
                 : "=r"(r[0]), "=r"(r[1]), "=r"(r[2]), "=r"(r[3]) : "r"(a));
}
__device__ __forceinline__ void ldm_x4_t(uint32_t r[4], uint32_t a) {
    asm volatile("ldmatrix.sync.aligned.m8n8.x4.trans.shared.b16 {%0,%1,%2,%3}, [%4];"
                 : "=r"(r[0]), "=r"(r[1]), "=r"(r[2]), "=r"(r[3]) : "r"(a));
}
__device__ __forceinline__ uint32_t packh2(float x, float y) {
    __half2 h = __floats2half2_rn(x, y);
    return *(uint32_t*)&h;
}
__device__ __forceinline__ uint32_t ex2_h2(uint32_t h) {
    uint32_t r;
    asm("ex2.approx.f16x2 %0, %1;" : "=r"(r) : "r"(h));
    return r;
}

// ---------------------------------------------------------------------------
// Fused prepass: convert x, Wq, Wk, Wv, Wo fp32 -> fp16 in ONE launch
// ---------------------------------------------------------------------------
#define NX4 (N_*D_/4)
#define NW4 (D_*D_/4)

__global__ __launch_bounds__(256)
void cvt_all_kernel(const float* __restrict__ x,
                    const float* __restrict__ Wq,
                    const float* __restrict__ Wk,
                    const float* __restrict__ Wv,
                    const float* __restrict__ Wo,
                    __half* __restrict__ xh,
                    __half* __restrict__ wh3,
                    __half* __restrict__ wh)
{
    int i = blockIdx.x * blockDim.x + threadIdx.x;
    const float* src; __half* dst; int off;
    if (i < NX4)              { src = x;  dst = xh;                     off = i; }
    else if (i < NX4 + NW4)   { src = Wq; dst = wh3;                    off = i - NX4; }
    else if (i < NX4 + 2*NW4) { src = Wk; dst = wh3 + (size_t)D_*D_;    off = i - NX4 - NW4; }
    else if (i < NX4 + 3*NW4) { src = Wv; dst = wh3 + (size_t)2*D_*D_;  off = i - NX4 - 2*NW4; }
    else                      { src = Wo; dst = wh;                     off = i - NX4 - 3*NW4; }
    float4 v = ((const float4*)src)[off];
    uint2 o;
    o.x = packh2(v.x, v.y);
    o.y = packh2(v.z, v.w);
    ((uint2*)dst)[off] = o;
}

// ---------------------------------------------------------------------------
// fp16 tensor-core GEMM, K chunk = 64 halves (128B rows), 3-stage ring,
// one barrier per chunk (16 total). Stride 144B: conflict-free ldmatrix.
// ---------------------------------------------------------------------------
#define TM 128
#define TN 128
#define KCH 64
#define NCH (D_/KCH)                // 16
#define GSTG 3
#define RSB 144
#define TILE_BYTES (128*RSB)        // 18432
#define STAGE_BYTES (2*TILE_BYTES)  // 36864
#define GEMM_SMEM (GSTG*STAGE_BYTES) // 110592

__device__ __forceinline__ void load_chunk_h(const __half* __restrict__ A,
                                             const __half* __restrict__ W,
                                             int row0, int col0, int c,
                                             char* stage, int tid)
{
    if (c < NCH) {
        const uint32_t abase = (uint32_t)__cvta_generic_to_shared(stage);
        const uint32_t bbase = abase + TILE_BYTES;
        const char* asrc = (const char*)(A + (size_t)row0 * D_ + c * KCH);
        const char* bsrc = (const char*)(W + (size_t)col0 * D_ + c * KCH);
#pragma unroll
        for (int i = 0; i < 4; i++) {          // 128 rows x 128B (8 cp16/row)
            int idx = tid + (i << 8);
            int r = idx >> 3, c16 = idx & 7;
            cp16(abase + (uint32_t)(r * RSB + c16 * 16),
                 asrc + (size_t)r * (D_*2) + c16 * 16);
        }
#pragma unroll
        for (int i = 0; i < 4; i++) {
            int idx = tid + (i << 8);
            int r = idx >> 3, c16 = idx & 7;
            cp16(bbase + (uint32_t)(r * RSB + c16 * 16),
                 bsrc + (size_t)r * (D_*2) + c16 * 16);
        }
    }
    cp_commit();
}

template<int OUT_HALF>
__device__ __forceinline__ void gemm_body_h(const __half* __restrict__ A,
                                            const __half* __restrict__ W,
                                            const float* __restrict__ bias,
                                            void* __restrict__ C,
                                            int row0, int col0, char* sm)
{
    const int tid  = threadIdx.x;
    const int lane = tid & 31;
    const int warp = tid >> 5;
    const int wm   = warp & 3;
    const int wn   = warp >> 2;
    const int gr = lane >> 2;
    const int lc = lane & 3;

    const uint32_t aoff = (uint32_t)((wm * 32 + (lane & 15)) * RSB + (lane >> 4) * 16);
    const uint32_t boff = (uint32_t)((wn * 64 + (lane & 7) + ((lane >> 4) << 3)) * RSB
                                     + ((lane >> 3) & 1) * 16);
    const uint32_t smb = (uint32_t)__cvta_generic_to_shared(sm);

    float c_f[2][8][4];
#pragma unroll
    for (int mi = 0; mi < 2; mi++)
#pragma unroll
        for (int ni = 0; ni < 8; ni++)
#pragma unroll
            for (int j = 0; j < 4; j++) c_f[mi][ni][j] = 0.f;

    load_chunk_h(A, W, row0, col0, 0, sm, tid);
    load_chunk_h(A, W, row0, col0, 1, sm + STAGE_BYTES, tid);

    int stg = 0;
    for (int kt = 0; kt < NCH; kt++) {
        cp_wait<GSTG - 2>();
        __syncthreads();

        int wst = stg + 2; if (wst >= GSTG) wst -= GSTG;
        load_chunk_h(A, W, row0, col0, kt + 2, sm + wst * STAGE_BYTES, tid);

        const uint32_t Ab = smb + stg * STAGE_BYTES;
        const uint32_t Bb = Ab + TILE_BYTES;

#pragma unroll
        for (int ks = 0; ks < 4; ks++) {       // 4 x k16 per 64-half chunk
            uint32_t a0[4], a1[4];
            ldm_x4(a0, Ab + aoff + ks * 32);
            ldm_x4(a1, Ab + aoff + 16 * RSB + ks * 32);
#pragma unroll
            for (int p = 0; p < 4; p++) {
                uint32_t br[4];
                ldm_x4(br, Bb + boff + (uint32_t)(p * 16 * RSB + ks * 32));
                mma_f16(c_f[0][2*p],   a0, br);
                mma_f16(c_f[0][2*p+1], a0, br + 2);
                mma_f16(c_f[1][2*p],   a1, br);
                mma_f16(c_f[1][2*p+1], a1, br + 2);
            }
        }
        if (++stg == GSTG) stg = 0;
    }

#pragma unroll
    for (int ni = 0; ni < 8; ni++) {
        int col = col0 + wn * 64 + ni * 8 + lc * 2;
        float2 bb = *(const float2*)(bias + col);
#pragma unroll
        for (int mi = 0; mi < 2; mi++) {
            int r = row0 + wm * 32 + mi * 16 + gr;
            float o00 = c_f[mi][ni][0] + bb.x;
            float o01 = c_f[mi][ni][1] + bb.y;
            float o10 = c_f[mi][ni][2] + bb.x;
            float o11 = c_f[mi][ni][3] + bb.y;
            if (OUT_HALF) {
                __half* Ch = (__half*)C;
                *(uint32_t*)(Ch + (size_t)r * D_ + col)       = packh2(o00, o01);
                *(uint32_t*)(Ch + (size_t)(r + 8) * D_ + col) = packh2(o10, o11);
            } else {
                float* Cf = (float*)C;
                *(float2*)(Cf + (size_t)r * D_ + col)       = make_float2(o00, o01);
                *(float2*)(Cf + (size_t)(r + 8) * D_ + col) = make_float2(o10, o11);
            }
        }
    }
}

__global__ __launch_bounds__(256, 2)
void gemm_qkv_kernel(const __half* __restrict__ A,
                     const __half* __restrict__ W3,
                     const float* __restrict__ bq,
                     const float* __restrict__ bk,
                     const float* __restrict__ bv,
                     __half* __restrict__ Cq,
                     __half* __restrict__ Ck,
                     __half* __restrict__ Cv)
{
    extern __shared__ char smraw[];
    const int sel  = blockIdx.x >> 3;
    const int col0 = (blockIdx.x & 7) * TN;
    const int row0 = blockIdx.y * TM;
    const __half* W = W3 + (size_t)sel * D_ * D_;
    const float* bias = (sel == 0) ? bq : (sel == 1) ? bk : bv;
    __half* C = (sel == 0) ? Cq : (sel == 1) ? Ck : Cv;
    gemm_body_h<1>(A, W, bias, C, row0, col0, smraw);
}

__global__ __launch_bounds__(256, 2)
void gemm_o_kernel(const __half* __restrict__ A,
                   const __half* __restrict__ W,
                   const float* __restrict__ bias,
                   float* __restrict__ C)
{
    extern __shared__ char smraw[];
    gemm_body_h<0>(A, W, bias, C, blockIdx.y * TM, blockIdx.x * TN, smraw);
}

// ---------------------------------------------------------------------------
// Flash attention, fp16 + ldmatrix, 3-stage KV ring.
// Softmax exp via ex2.approx.f16x2 (2 P-elements per MUFU op); ex2 outputs
// ARE the PV A-fragments (no repack).
// ---------------------------------------------------------------------------
#define ASTG 3
#define AK_STRB 144
#define ATILE_BYTES (64*AK_STRB)
#define ASTAGE_BYTES (2*ATILE_BYTES)
#define ATTN_SMEM (ASTG*ASTAGE_BYTES)     // 55296
#define NKT (S_/64)

__device__ __forceinline__ void attn_load_kv(const __half* __restrict__ kg,
                                             const __half* __restrict__ vg,
                                             int kt, char* stage, int tid)
{
    if (kt < NKT) {
        const uint32_t kb = (uint32_t)__cvta_generic_to_shared(stage);
        const uint32_t vb = kb + ATILE_BYTES;
        const char* ksrc = (const char*)(kg + (size_t)kt * 64 * D_);
        const char* vsrc = (const char*)(vg + (size_t)kt * 64 * D_);
#pragma unroll
        for (int i = 0; i < 4; i++) {
            int idx = tid + (i << 7);
            int r = idx >> 3, c16 = idx & 7;
            cp16(kb + (uint32_t)(r * AK_STRB + c16 * 16),
                 ksrc + (size_t)r * (D_*2) + c16 * 16);
        }
#pragma unroll
        for (int i = 0; i < 4; i++) {
            int idx = tid + (i << 7);
            int r = idx >> 3, c16 = idx & 7;
            cp16(vb + (uint32_t)(r * AK_STRB + c16 * 16),
                 vsrc + (size_t)r * (D_*2) + c16 * 16);
        }
    }
    cp_commit();
}

__global__ __launch_bounds__(128, 4)
void attn_mma_kernel(const __half* __restrict__ Q,
                     const __half* __restrict__ Kg,
                     const __half* __restrict__ Vg,
                     __half* __restrict__ O)
{
    extern __shared__ char smraw[];
    const int tid  = threadIdx.x;
    const int lane = tid & 31;
    const int warp = tid >> 5;
    const int gr   = lane >> 2;
    const int lc   = lane & 3;

    const int q0 = blockIdx.x * 64;
    const int bh = blockIdx.y;
    const int b  = bh >> 4;
    const int h  = bh & 15;

    const __half* qg = Q  + ((size_t)(b * S_ + q0)) * D_ + h * HD_;
    const __half* kg = Kg + ((size_t)b * S_) * D_ + h * HD_;
    const __half* vg = Vg + ((size_t)b * S_) * D_ + h * HD_;

    attn_load_kv(kg, vg, 0, smraw, tid);
    attn_load_kv(kg, vg, 1, smraw + ASTAGE_BYTES, tid);

    const uint32_t koff = (uint32_t)(((lane & 7) + ((lane >> 4) << 3)) * AK_STRB
                                     + ((lane >> 3) & 1) * 16);
    const uint32_t voff = (uint32_t)(((lane & 7) + (((lane >> 3) & 1) << 3)) * AK_STRB
                                     + (lane >> 4) * 16);
    const uint32_t smb = (uint32_t)__cvta_generic_to_shared(smraw);

    // Q fragments straight from gmem (scale 2^-3 exact in fp16)
    uint32_t qf[4][4];
    {
        const __half2 sc = __floats2half2_rn(0.125f, 0.125f);
        const __half* q0p = qg + (size_t)(warp * 16 + gr) * D_;
        const __half* q1p = q0p + (size_t)8 * D_;
#pragma unroll
        for (int ks = 0; ks < 4; ks++) {
            const int k0 = ks * 16 + 2 * lc;
            __half2 h0 = __hmul2(*(const __half2*)(q0p + k0), sc);
            __half2 h1 = __hmul2(*(const __half2*)(q1p + k0), sc);
            __half2 h2 = __hmul2(*(const __half2*)(q0p + k0 + 8), sc);
            __half2 h3 = __hmul2(*(const __half2*)(q1p + k0 + 8), sc);
            qf[ks][0] = *(uint32_t*)&h0;
            qf[ks][1] = *(uint32_t*)&h1;
            qf[ks][2] = *(uint32_t*)&h2;
            qf[ks][3] = *(uint32_t*)&h3;
        }
    }

    float co[8][4];
#pragma unroll
    for (int ni = 0; ni < 8; ni++)
#pragma unroll
        for (int j = 0; j < 4; j++) co[ni][j] = 0.f;
    float m0 = -1e30f, m1 = -1e30f, l0 = 0.f, l1 = 0.f;

    const float L2E = 1.4426950408889634f;

    int stg = 0;
    for (int kt = 0; kt < NKT; kt++) {
        cp_wait<1>();
        __syncthreads();

        int wst = stg + 2; if (wst >= ASTG) wst -= ASTG;
        attn_load_kv(kg, vg, kt + 2, smraw + wst * ASTAGE_BYTES, tid);

        const uint32_t Kb = smb + stg * ASTAGE_BYTES;
        const uint32_t Vb = Kb + ATILE_BYTES;

        // --- S = (scaled Q) @ K^T ---
        float c[8][4];
#pragma unroll
        for (int ni = 0; ni < 8; ni++)
#pragma unroll
            for (int j = 0; j < 4; j++) c[ni][j] = 0.f;

#pragma unroll
        for (int ks = 0; ks < 4; ks++) {
#pragma unroll
            for (int p = 0; p < 4; p++) {
                uint32_t br[4];
                ldm_x4(br, Kb + koff + (uint32_t)(p * 16 * AK_STRB + ks * 32));
                mma_f16(c[2*p],   qf[ks], br);
                mma_f16(c[2*p+1], qf[ks], br + 2);
            }
        }

        // --- online softmax (exp via ex2.approx.f16x2) ---
        float mt0 = fmaxf(c[0][0], c[0][1]);
        float mt1 = fmaxf(c[0][2], c[0][3]);
#pragma unroll
        for (int ni = 1; ni < 8; ni++) {
            mt0 = fmaxf(mt0, fmaxf(c[ni][0], c[ni][1]));
            mt1 = fmaxf(mt1, fmaxf(c[ni][2], c[ni][3]));
        }
        mt0 = fmaxf(mt0, __shfl_xor_sync(0xffffffffu, mt0, 1));
        mt0 = fmaxf(mt0, __shfl_xor_sync(0xffffffffu, mt0, 2));
        mt1 = fmaxf(mt1, __shfl_xor_sync(0xffffffffu, mt1, 1));
        mt1 = fmaxf(mt1, __shfl_xor_sync(0xffffffffu, mt1, 2));

        const float mn0 = fmaxf(m0, mt0);
        const float mn1 = fmaxf(m1, mt1);
        const float al0 = __expf(m0 - mn0);
        const float al1 = __expf(m1 - mn1);
        const float bb0 = -mn0 * L2E;
        const float bb1 = -mn1 * L2E;

        uint32_t pr[8][2];    // fp16x2 P values: [ni][0]=cols(0,1) row gr, [ni][1]=cols(2,3) row gr+8
        float rs0 = 0.f, rs1 = 0.f;
#pragma unroll
        for (int ni = 0; ni < 8; ni++) {
            float e0 = fmaf(c[ni][0], L2E, bb0);
            float e1 = fmaf(c[ni][1], L2E, bb0);
            float e2 = fmaf(c[ni][2], L2E, bb1);
            float e3 = fmaf(c[ni][3], L2E, bb1);
            uint32_t p01 = ex2_h2(packh2(e0, e1));
            uint32_t p23 = ex2_h2(packh2(e2, e3));
            pr[ni][0] = p01;
            pr[ni][1] = p23;
            float2 f01 = __half22float2(*(__half2*)&p01);
            float2 f23 = __half22float2(*(__half2*)&p23);
            rs0 += f01.x + f01.y;
            rs1 += f23.x + f23.y;
        }
        rs0 += __shfl_xor_sync(0xffffffffu, rs0, 1);
        rs0 += __shfl_xor_sync(0xffffffffu, rs0, 2);
        rs1 += __shfl_xor_sync(0xffffffffu, rs1, 1);
        rs1 += __shfl_xor_sync(0xffffffffu, rs1, 2);

        l0 = l0 * al0 + rs0;  m0 = mn0;
        l1 = l1 * al1 + rs1;  m1 = mn1;

#pragma unroll
        for (int ni = 0; ni < 8; ni++) {
            co[ni][0] *= al0; co[ni][1] *= al0;
            co[ni][2] *= al1; co[ni][3] *= al1;
        }

        // --- O += P @ V : ex2 outputs are the A-fragments directly ---
#pragma unroll
        for (int ks = 0; ks < 4; ks++) {
            uint32_t af[4];
            af[0] = pr[2*ks][0];
            af[1] = pr[2*ks][1];
            af[2] = pr[2*ks+1][0];
            af[3] = pr[2*ks+1][1];
#pragma unroll
            for (int p = 0; p < 4; p++) {
                uint32_t br[4];
                ldm_x4_t(br, Vb + voff + (uint32_t)(ks * 16 * AK_STRB + p * 32));
                mma_f16(co[2*p],   af, br);
                mma_f16(co[2*p+1], af, br + 2);
            }
        }

        if (++stg == ASTG) stg = 0;
    }

    // --- finalize ---
    const float inv0 = 1.f / l0;
    const float inv1 = 1.f / l1;
    const int n0 = b * S_ + q0 + warp * 16 + gr;
#pragma unroll
    for (int ni = 0; ni < 8; ni++) {
        const int col = h * HD_ + ni * 8 + lc * 2;
        *(uint32_t*)(O + (size_t)n0 * D_ + col) =
            packh2(co[ni][0] * inv0, co[ni][1] * inv0);
        *(uint32_t*)(O + (size_t)(n0 + 8) * D_ + col) =
            packh2(co[ni][2] * inv1, co[ni][3] * inv1);
    }
}

// ---------------------------------------------------------------------------
extern "C" void kernel_launch(void* const* d_in, const int* in_sizes, int n_in,
                              void* d_out, int out_size)
{
    const float* x  = (const float*)d_in[0];
    const float* Wq = (const float*)d_in[1];
    const float* bq = (const float*)d_in[2];
    const float* Wk = (const float*)d_in[3];
    const float* bk = (const float*)d_in[4];
    const float* Wv = (const float*)d_in[5];
    const float* bv = (const float*)d_in[6];
    const float* Wo = (const float*)d_in[7];
    const float* bo = (const float*)d_in[8];
    float* out = (float*)d_out;

    __half *xh, *wh3, *wh, *qh, *kh, *vh, *oh;
    cudaGetSymbolAddress((void**)&xh,  g_xh);
    cudaGetSymbolAddress((void**)&wh3, g_wh3);
    cudaGetSymbolAddress((void**)&wh,  g_wh);
    cudaGetSymbolAddress((void**)&qh,  g_qh);
    cudaGetSymbolAddress((void**)&kh,  g_kh);
    cudaGetSymbolAddress((void**)&vh,  g_vh);
    cudaGetSymbolAddress((void**)&oh,  g_oh);

    cudaFuncSetAttribute(gemm_qkv_kernel,
                         cudaFuncAttributeMaxDynamicSharedMemorySize, GEMM_SMEM);
    cudaFuncSetAttribute(gemm_o_kernel,
                         cudaFuncAttributeMaxDynamicSharedMemorySize, GEMM_SMEM);
    cudaFuncSetAttribute(attn_mma_kernel,
                         cudaFuncAttributeMaxDynamicSharedMemorySize, ATTN_SMEM);

    const int ntot4 = NX4 + 4 * NW4;
    cvt_all_kernel<<<ntot4 / 256, 256>>>(x, Wq, Wk, Wv, Wo, xh, wh3, wh);

    gemm_qkv_kernel<<<dim3(24, N_ / TM), 256, GEMM_SMEM>>>(
        xh, wh3, bq, bk, bv, qh, kh, vh);

    attn_mma_kernel<<<dim3(S_ / 64, B_ * H_), 128, ATTN_SMEM>>>(qh, kh, vh, oh);

    gemm_o_kernel<<<dim3(D_ / TN, N_ / TM), 256, GEMM_SMEM>>>(oh, wh, bo, out);
}